// round 12
// baseline (speedup 1.0000x reference)
#include <cuda_runtime.h>
#include <cuda_bf16.h>
#include <cstdint>
#include <cstddef>

#define B_   64
#define S_   256
#define H_   512
#define E_   256
#define V_   32000
#define ML_  32256
#define D2H  1024
#define XW   1536
#define X1W  1280

// warp-level bf16 HMMA, fp32 accumulate
#define MMA_BF16(d, a, b) \
    asm volatile("mma.sync.aligned.m16n8k16.row.col.f32.bf16.bf16.f32 " \
        "{%0,%1,%2,%3}, {%4,%5,%6,%7}, {%8,%9}, {%0,%1,%2,%3};" \
        : "+f"((d)[0]), "+f"((d)[1]), "+f"((d)[2]), "+f"((d)[3]) \
        : "r"((a)[0]), "r"((a)[1]), "r"((a)[2]), "r"((a)[3]), "r"((b)[0]), "r"((b)[1]))

__device__ __forceinline__ void split4(float4 v, uint2& hi, uint2& lo) {
    __nv_bfloat162 h01 = make_bfloat162(__float2bfloat16(v.x), __float2bfloat16(v.y));
    __nv_bfloat162 h23 = make_bfloat162(__float2bfloat16(v.z), __float2bfloat16(v.w));
    __nv_bfloat162 l01 = make_bfloat162(
        __float2bfloat16(v.x - __bfloat162float(h01.x)),
        __float2bfloat16(v.y - __bfloat162float(h01.y)));
    __nv_bfloat162 l23 = make_bfloat162(
        __float2bfloat16(v.z - __bfloat162float(h23.x)),
        __float2bfloat16(v.w - __bfloat162float(h23.y)));
    hi = make_uint2(*(uint32_t*)&h01, *(uint32_t*)&h23);
    lo = make_uint2(*(uint32_t*)&l01, *(uint32_t*)&l23);
}

// ---- scratch ----
__device__ float g_x1[B_ * X1W];
__device__ float g_x [B_ * XW];
__device__ float g_state[B_ * H_];
__device__ float g_logits[B_ * ML_];
__device__ float g_part [8 * B_ * XW];
__device__ float g_part2[8 * B_ * XW];
__device__ float g_F[(size_t)B_ * S_ * H_];    // tanh(enc@W_c + b_c), 32 MB

// ---- generic HMMA GEMM body: C[64,N] = A[64,K] @ B[N,K]^T, bf16 3-split ----
#define HS 72
__device__ __forceinline__ void hmma64_body(
    const float* __restrict__ A, int lda, const float* __restrict__ Bm,
    const float* __restrict__ bias, float* __restrict__ C, int ldc,
    float* __restrict__ P, int N, int K, int kSplit,
    int bx, int by, uint8_t* __restrict__ smem)
{
    uint8_t* AhiS = smem;
    uint8_t* AloS = smem + 64 * HS;
    uint8_t* BhiS = smem + 128 * HS;
    uint8_t* BloS = smem + 256 * HS;

    const int tid = threadIdx.x, wid = tid >> 5, lane = tid & 31;
    const int g = lane >> 2, tg = lane & 3;
    const int wm = wid >> 2, wn = wid & 3;
    const int n0 = bx * 128;
    const int kLen = K / kSplit, k0 = by * kLen;
    const int nch = kLen >> 5;

    const int lrow = tid >> 1, lhalf = tid & 1;
    const float* Bsrc = Bm + (size_t)(n0 + lrow) * K + k0 + lhalf * 16;
    uint8_t* BdH = BhiS + lrow * HS + lhalf * 32;
    uint8_t* BdL = BloS + lrow * HS + lhalf * 32;
    const float* Asrc = A + (size_t)lrow * lda + k0 + lhalf * 16;
    uint8_t* AdH = AhiS + lrow * HS + lhalf * 32;
    uint8_t* AdL = AloS + lrow * HS + lhalf * 32;

    float acc[2][4][4];
    #pragma unroll
    for (int mi = 0; mi < 2; mi++)
        #pragma unroll
        for (int ni = 0; ni < 4; ni++)
            #pragma unroll
            for (int q = 0; q < 4; q++) acc[mi][ni][q] = 0.f;

    for (int kc = 0; kc < nch; kc++) {
        #pragma unroll
        for (int i = 0; i < 4; i++) {
            uint2 hi, lo;
            split4(*(const float4*)(Bsrc + kc * 32 + i * 4), hi, lo);
            *(uint2*)(BdH + i * 8) = hi;
            *(uint2*)(BdL + i * 8) = lo;
            if (tid < 128) {
                split4(*(const float4*)(Asrc + kc * 32 + i * 4), hi, lo);
                *(uint2*)(AdH + i * 8) = hi;
                *(uint2*)(AdL + i * 8) = lo;
            }
        }
        __syncthreads();
        #pragma unroll
        for (int ks = 0; ks < 2; ks++) {
            const int ko = ks * 32 + tg * 4;
            uint32_t ah[2][4], al[2][4];
            #pragma unroll
            for (int mi = 0; mi < 2; mi++) {
                const uint8_t* p = AhiS + (size_t)(wm * 32 + mi * 16 + g) * HS + ko;
                const uint8_t* q = AloS + (size_t)(wm * 32 + mi * 16 + g) * HS + ko;
                ah[mi][0] = *(const uint32_t*)(p);
                ah[mi][1] = *(const uint32_t*)(p + 8 * HS);
                ah[mi][2] = *(const uint32_t*)(p + 16);
                ah[mi][3] = *(const uint32_t*)(p + 8 * HS + 16);
                al[mi][0] = *(const uint32_t*)(q);
                al[mi][1] = *(const uint32_t*)(q + 8 * HS);
                al[mi][2] = *(const uint32_t*)(q + 16);
                al[mi][3] = *(const uint32_t*)(q + 8 * HS + 16);
            }
            #pragma unroll
            for (int ni = 0; ni < 4; ni++) {
                const uint8_t* p = BhiS + (size_t)(wn * 32 + ni * 8 + g) * HS + ko;
                const uint8_t* q = BloS + (size_t)(wn * 32 + ni * 8 + g) * HS + ko;
                uint32_t bh[2] = { *(const uint32_t*)(p), *(const uint32_t*)(p + 16) };
                uint32_t bl[2] = { *(const uint32_t*)(q), *(const uint32_t*)(q + 16) };
                #pragma unroll
                for (int mi = 0; mi < 2; mi++) {
                    MMA_BF16(acc[mi][ni], ah[mi], bh);
                    MMA_BF16(acc[mi][ni], ah[mi], bl);
                    MMA_BF16(acc[mi][ni], al[mi], bh);
                }
            }
        }
        __syncthreads();
    }

    if (kSplit == 1) {
        #pragma unroll
        for (int mi = 0; mi < 2; mi++) {
            int r = wm * 32 + mi * 16 + g;
            #pragma unroll
            for (int ni = 0; ni < 4; ni++) {
                int c = n0 + wn * 32 + ni * 8 + 2 * tg;
                float b0 = bias ? bias[c] : 0.f, b1 = bias ? bias[c+1] : 0.f;
                C[(size_t)r * ldc + c]           = acc[mi][ni][0] + b0;
                C[(size_t)r * ldc + c + 1]       = acc[mi][ni][1] + b1;
                C[(size_t)(r + 8) * ldc + c]     = acc[mi][ni][2] + b0;
                C[(size_t)(r + 8) * ldc + c + 1] = acc[mi][ni][3] + b1;
            }
        }
    } else {
        float* Pz = P + (size_t)by * 64 * N;
        #pragma unroll
        for (int mi = 0; mi < 2; mi++) {
            int r = wm * 32 + mi * 16 + g;
            #pragma unroll
            for (int ni = 0; ni < 4; ni++) {
                int c = n0 + wn * 32 + ni * 8 + 2 * tg;
                Pz[(size_t)r * N + c]           = acc[mi][ni][0];
                Pz[(size_t)r * N + c + 1]       = acc[mi][ni][1];
                Pz[(size_t)(r + 8) * N + c]     = acc[mi][ni][2];
                Pz[(size_t)(r + 8) * N + c + 1] = acc[mi][ni][3];
            }
        }
    }
}

// ---- scoreF body: F[b,s,h] = tanh(enc@W_c^T + b_c), 128x128 tile (R7 math) ----
__device__ __forceinline__ void scoreF_body(
    const float* __restrict__ enc, const float* __restrict__ W_c,
    const float* __restrict__ b_c, int f, uint8_t* __restrict__ smem)
{
    const int sx = f & 1, ny = (f >> 1) & 3, b = f >> 3;
    uint8_t* Ahi = smem;
    uint8_t* Alo = smem + 128 * HS;
    uint8_t* Bhi = smem + 256 * HS;
    uint8_t* Blo = smem + 384 * HS;

    const int tid  = threadIdx.x;
    const int wid  = tid >> 5, lane = tid & 31;
    const int g    = lane >> 2, tg = lane & 3;
    const int wm   = wid >> 2,  wn = wid & 3;
    const int s0   = sx * 128, n0 = ny * 128;

    const int lrow = tid >> 1, lhalf = tid & 1;
    const float* Asrc = enc + ((size_t)(b * S_ + s0 + lrow)) * D2H + lhalf * 16;
    const float* Bsrc = W_c + ((size_t)(n0 + lrow)) * D2H + lhalf * 16;
    uint8_t* AdH = Ahi + lrow * HS + lhalf * 32;
    uint8_t* AdL = Alo + lrow * HS + lhalf * 32;
    uint8_t* BdH = Bhi + lrow * HS + lhalf * 32;
    uint8_t* BdL = Blo + lrow * HS + lhalf * 32;

    float acc[4][4][4];
    #pragma unroll
    for (int mi = 0; mi < 4; mi++)
        #pragma unroll
        for (int ni = 0; ni < 4; ni++)
            #pragma unroll
            for (int q = 0; q < 4; q++) acc[mi][ni][q] = 0.f;

    for (int kc = 0; kc < 32; kc++) {
        #pragma unroll
        for (int i = 0; i < 4; i++) {
            uint2 hi, lo;
            split4(*(const float4*)(Asrc + kc * 32 + i * 4), hi, lo);
            *(uint2*)(AdH + i * 8) = hi;
            *(uint2*)(AdL + i * 8) = lo;
            split4(*(const float4*)(Bsrc + kc * 32 + i * 4), hi, lo);
            *(uint2*)(BdH + i * 8) = hi;
            *(uint2*)(BdL + i * 8) = lo;
        }
        __syncthreads();
        #pragma unroll
        for (int ks = 0; ks < 2; ks++) {
            const int ko = ks * 32 + tg * 4;
            uint32_t ah[4][4], al[4][4];
            #pragma unroll
            for (int mi = 0; mi < 4; mi++) {
                const uint8_t* p = Ahi + (size_t)(wm * 64 + mi * 16 + g) * HS + ko;
                const uint8_t* q = Alo + (size_t)(wm * 64 + mi * 16 + g) * HS + ko;
                ah[mi][0] = *(const uint32_t*)(p);
                ah[mi][1] = *(const uint32_t*)(p + 8 * HS);
                ah[mi][2] = *(const uint32_t*)(p + 16);
                ah[mi][3] = *(const uint32_t*)(p + 8 * HS + 16);
                al[mi][0] = *(const uint32_t*)(q);
                al[mi][1] = *(const uint32_t*)(q + 8 * HS);
                al[mi][2] = *(const uint32_t*)(q + 16);
                al[mi][3] = *(const uint32_t*)(q + 8 * HS + 16);
            }
            #pragma unroll
            for (int ni = 0; ni < 4; ni++) {
                const uint8_t* p = Bhi + (size_t)(wn * 32 + ni * 8 + g) * HS + ko;
                const uint8_t* q = Blo + (size_t)(wn * 32 + ni * 8 + g) * HS + ko;
                uint32_t bh[2] = { *(const uint32_t*)(p), *(const uint32_t*)(p + 16) };
                uint32_t bl[2] = { *(const uint32_t*)(q), *(const uint32_t*)(q + 16) };
                #pragma unroll
                for (int mi = 0; mi < 4; mi++) {
                    MMA_BF16(acc[mi][ni], ah[mi], bh);
                    MMA_BF16(acc[mi][ni], ah[mi], bl);
                    MMA_BF16(acc[mi][ni], al[mi], bh);
                }
            }
        }
        __syncthreads();
    }

    // epilogue: tanh(+bias) -> g_F (no state needed)
    #pragma unroll
    for (int ni = 0; ni < 4; ni++) {
        int c0 = n0 + wn * 32 + ni * 8 + 2 * tg;
        float bc0 = b_c[c0], bc1 = b_c[c0 + 1];
        #pragma unroll
        for (int mi = 0; mi < 4; mi++) {
            int r = s0 + wm * 64 + mi * 16 + g;
            float* F0 = g_F + ((size_t)b * S_ + r) * H_ + c0;
            F0[0] = tanhf(acc[mi][ni][0] + bc0);
            F0[1] = tanhf(acc[mi][ni][1] + bc1);
            float* F1 = g_F + ((size_t)b * S_ + r + 8) * H_ + c0;
            F1[0] = tanhf(acc[mi][ni][2] + bc0);
            F1[1] = tanhf(acc[mi][ni][3] + bc1);
        }
    }
}

// ---- attention body (256 threads, one block per batch) ----
__device__ __forceinline__ void attn_body(
    const float* __restrict__ enc, const int* __restrict__ seq,
    const int* __restrict__ input_idx, const float* __restrict__ ppc,
    const float* __restrict__ table, const float* __restrict__ b_aw,
    int b, uint8_t* __restrict__ smraw)
{
    float* sm  = (float*)smraw;          // 1024
    float* wv  = sm + D2H;               // 256
    float* swv = wv + S_;                // 256
    float* red = swv + S_;               // 256
    const int t = threadIdx.x;

    {
        int idx = input_idx[b];
        if (idx >= V_) idx = 2;
        g_x1[b * X1W + D2H + t] = table[(size_t)idx * E_ + t];
    }
    #pragma unroll
    for (int j = 0; j < 4; j++) {
        int d = t + j * 256;
        float s = b_aw[d];
        #pragma unroll
        for (int z = 0; z < 8; z++) s += g_part[(size_t)z * 64 * D2H + b * D2H + d];
        sm[d] = s;
    }
    {
        int idxb = input_idx[b];
        swv[t] = (seq[b * S_ + t] == idxb) ? ppc[b * S_ + t] : 0.f;
    }
    __syncthreads();

    const int warp = t >> 5, lane = t & 31;
    for (int r = 0; r < 32; r++) {
        int s = warp * 32 + r;
        const float4* row = (const float4*)(enc + ((size_t)b * S_ + s) * D2H);
        float sum = 0.f;
        #pragma unroll
        for (int qi = 0; qi < 8; qi++) {
            int q = lane + qi * 32;
            float4 v = row[q];
            sum += v.x*sm[q*4] + v.y*sm[q*4+1] + v.z*sm[q*4+2] + v.w*sm[q*4+3];
        }
        #pragma unroll
        for (int o = 16; o; o >>= 1) sum += __shfl_down_sync(0xffffffffu, sum, o);
        if (lane == 0) wv[s] = sum;
    }
    __syncthreads();

    red[t] = wv[t];
    __syncthreads();
    for (int o = 128; o; o >>= 1) { if (t < o) red[t] = fmaxf(red[t], red[t+o]); __syncthreads(); }
    float mx = red[0];
    __syncthreads();
    wv[t] = expf(wv[t] - mx);
    red[t] = wv[t];
    __syncthreads();
    for (int o = 128; o; o >>= 1) { if (t < o) red[t] += red[t+o]; __syncthreads(); }
    float inv = 1.f / red[0];
    __syncthreads();
    wv[t] *= inv;
    __syncthreads();

    float ctx[4] = {0.f, 0.f, 0.f, 0.f}, sel[4] = {0.f, 0.f, 0.f, 0.f};
    const float* e = enc + (size_t)b * S_ * D2H;
    #pragma unroll 8
    for (int s = 0; s < S_; s++) {
        float ws = wv[s], ss = swv[s];
        #pragma unroll
        for (int j = 0; j < 4; j++) {
            float v = e[(size_t)s * D2H + t + j * 256];
            ctx[j] = fmaf(ws, v, ctx[j]);
            sel[j] = fmaf(ss, v, sel[j]);
        }
    }
    #pragma unroll
    for (int j = 0; j < 4; j++) {
        int d = t + j * 256;
        g_x1[b * X1W + d]     = ctx[j];
        g_x [b * XW + H_ + d] = sel[j];
    }
}

// ---- scorec dot body: logits[b, V_+s] = sum_h F[b,s,h] * state[b,h] ----
__device__ __forceinline__ void scorec_dot_body(int b, uint8_t* __restrict__ smraw)
{
    float* sst = (float*)smraw;          // 512 floats
    const int t = threadIdx.x, warp = t >> 5, lane = t & 31;
    for (int i = t; i < H_; i += 256) sst[i] = g_state[b * H_ + i];
    __syncthreads();
    for (int r = 0; r < 32; r++) {
        int s = warp * 32 + r;
        const float4* Fr = (const float4*)(g_F + ((size_t)b * S_ + s) * H_);
        float sum = 0.f;
        #pragma unroll
        for (int k = 0; k < 4; k++) {
            int q = lane + k * 32;
            float4 fv = Fr[q];
            sum += fv.x*sst[q*4] + fv.y*sst[q*4+1] + fv.z*sst[q*4+2] + fv.w*sst[q*4+3];
        }
        #pragma unroll
        for (int o = 16; o; o >>= 1) sum += __shfl_down_sync(0xffffffffu, sum, o);
        if (lane == 0) g_logits[(size_t)b * ML_ + V_ + s] = sum;
    }
}

// ================= mega launches (block-role packing, NO reg cap) =================
// L1: aw gemm (64) + gh gemm (96) + scoreF f=0..169
__global__ void __launch_bounds__(256) mega1(
    const float* __restrict__ pre_state, const float* __restrict__ W_aw,
    const float* __restrict__ W_hh,
    const float* __restrict__ enc, const float* __restrict__ W_c,
    const float* __restrict__ b_c)
{
    __shared__ __align__(16) uint8_t smem[512 * HS];
    int i = blockIdx.x;
    if (i < 64) {
        hmma64_body(pre_state, H_, W_aw, nullptr, nullptr, 0, g_part, D2H, H_, 8,
                    i & 7, i >> 3, smem);
    } else if (i < 160) {
        int j = i - 64;
        hmma64_body(pre_state, H_, W_hh, nullptr, nullptr, 0, g_part2, XW, H_, 8,
                    j % 12, j / 12, smem);
    } else {
        scoreF_body(enc, W_c, b_c, i - 160, smem);
    }
}

// L2: attn (64) + scoreF f=170..339
__global__ void __launch_bounds__(256) mega2(
    const float* __restrict__ enc, const int* __restrict__ seq,
    const int* __restrict__ input_idx, const float* __restrict__ ppc,
    const float* __restrict__ table, const float* __restrict__ b_aw,
    const float* __restrict__ W_c, const float* __restrict__ b_c)
{
    __shared__ __align__(16) uint8_t smem[512 * HS];
    int i = blockIdx.x;
    if (i < 64) attn_body(enc, seq, input_idx, ppc, table, b_aw, i, smem);
    else        scoreF_body(enc, W_c, b_c, 170 + (i - 64), smem);
}

// L3: W_ac gemm (32) + scoreF f=340..511
__global__ void __launch_bounds__(256) mega3(
    const float* __restrict__ x1, const float* __restrict__ W_ac,
    const float* __restrict__ enc, const float* __restrict__ W_c,
    const float* __restrict__ b_c)
{
    __shared__ __align__(16) uint8_t smem[512 * HS];
    int i = blockIdx.x;
    if (i < 32) hmma64_body(x1, X1W, W_ac, nullptr, nullptr, 0, g_part, H_, X1W, 8,
                            i & 3, i >> 2, smem);
    else        scoreF_body(enc, W_c, b_c, 340 + (i - 32), smem);
}

// L4: splitK reduce W_ac -> g_x[:,0:512]
__global__ void splitk_reduce(const float* __restrict__ bias,
                              float* __restrict__ C, int ldc,
                              const float* __restrict__ P, int N, int kSplit)
{
    int idx = blockIdx.x * blockDim.x + threadIdx.x;
    int total = 64 * N;
    if (idx >= total) return;
    int m = idx / N, n = idx - m * N;
    float s = bias ? bias[n] : 0.f;
    for (int z = 0; z < kSplit; z++) s += P[(size_t)z * total + idx];
    C[(size_t)m * ldc + n] = s;
}

// L5: gi gemm
__global__ void __launch_bounds__(256) gi_kernel(const float* __restrict__ W_ih)
{
    __shared__ __align__(16) uint8_t smem[384 * HS];
    hmma64_body(g_x, XW, W_ih, nullptr, nullptr, 0, g_part, XW, XW, 8,
                blockIdx.x, blockIdx.y, smem);
}

// L6: fused GRU (reduce gi/gh partials + gates)
__global__ void __launch_bounds__(512) gru_fused(
    const float* __restrict__ pre_state,
    const float* __restrict__ b_ih, const float* __restrict__ b_hh,
    float* __restrict__ out_state)
{
    const int b = blockIdx.x, h = threadIdx.x;
    float ir = b_ih[h], iz = b_ih[H_ + h], in_ = b_ih[2*H_ + h];
    float hr = b_hh[h], hz = b_hh[H_ + h], hn  = b_hh[2*H_ + h];
    #pragma unroll
    for (int z = 0; z < 8; z++) {
        size_t base = (size_t)z * 64 * XW + (size_t)b * XW;
        ir  += g_part [base + h];
        iz  += g_part [base + H_ + h];
        in_ += g_part [base + 2*H_ + h];
        hr  += g_part2[base + h];
        hz  += g_part2[base + H_ + h];
        hn  += g_part2[base + 2*H_ + h];
    }
    float r = 1.f / (1.f + expf(-(ir + hr)));
    float z = 1.f / (1.f + expf(-(iz + hz)));
    float n = tanhf(in_ + r * hn);
    float ps = pre_state[b * H_ + h];
    float st = (1.f - z) * n + z * ps;
    g_state[b * H_ + h] = st;
    out_state[b * H_ + h] = st;
}

// L7: score_g (250) + scorec dot (64)
__global__ void __launch_bounds__(256) mega7(
    const float* __restrict__ W_o, const float* __restrict__ b_o)
{
    __shared__ __align__(16) uint8_t smem[384 * HS];
    int i = blockIdx.x;
    if (i < V_ / 128) {
        hmma64_body(g_state, H_, W_o, b_o, g_logits, ML_, nullptr,
                    V_, H_, 1, i, 0, smem);
    } else {
        scorec_dot_body(i - V_ / 128, smem);
    }
}

// L8: big softmax + prob_g + prob_c scatter
__global__ void __launch_bounds__(1024) softmax_probc(
    const int* __restrict__ seq, float* __restrict__ out)
{
    const int b = blockIdx.x, t = threadIdx.x;
    float* row = g_logits + (size_t)b * ML_;
    float* orow = out + (size_t)b * ML_;
    __shared__ float sred[32];
    __shared__ float pc[S_];
    __shared__ int   sq[S_];

    if (t < S_) sq[t] = seq[b * S_ + t];

    float m = -1e30f;
    for (int i = t; i < ML_; i += 1024) m = fmaxf(m, row[i]);
    #pragma unroll
    for (int o = 16; o; o >>= 1) m = fmaxf(m, __shfl_xor_sync(0xffffffffu, m, o));
    if ((t & 31) == 0) sred[t >> 5] = m;
    __syncthreads();
    if (t < 32) {
        float x = sred[t];
        #pragma unroll
        for (int o = 16; o; o >>= 1) x = fmaxf(x, __shfl_xor_sync(0xffffffffu, x, o));
        sred[t] = x;
    }
    __syncthreads();
    m = sred[0];
    __syncthreads();
    float sum = 0.f;
    for (int i = t; i < ML_; i += 1024) {
        float e = expf(row[i] - m);
        row[i] = e;
        sum += e;
    }
    #pragma unroll
    for (int o = 16; o; o >>= 1) sum += __shfl_xor_sync(0xffffffffu, sum, o);
    if ((t & 31) == 0) sred[t >> 5] = sum;
    __syncthreads();
    if (t < 32) {
        float x = sred[t];
        #pragma unroll
        for (int o = 16; o; o >>= 1) x += __shfl_xor_sync(0xffffffffu, x, o);
        sred[t] = x;
    }
    __syncthreads();
    float inv = 1.f / sred[0];
    for (int i = t; i < ML_; i += 1024) {
        float v = row[i] * inv;
        if (i < V_) orow[i] = v;
        else { orow[i] = 0.f; pc[i - V_] = v; }
    }
    __syncthreads();

    if (t < S_) {
        int tok = sq[t];
        float s = 0.f;
        bool first = true;
        for (int i = 0; i < S_; i++) {
            bool mq = (sq[i] == tok);
            if (mq) s += pc[i];
            if (mq && i < t) first = false;
        }
        out[(size_t)B_ * ML_ + (size_t)B_ * H_ + b * S_ + t] = s;
        if (first) orow[tok] += s;
    }
}

// ---- launch ----
extern "C" void kernel_launch(void* const* d_in, const int* in_sizes, int n_in,
                              void* d_out, int out_size)
{
    const int*   input_idx = (const int*)  d_in[0];
    const float* enc       = (const float*)d_in[1];
    const int*   seq       = (const int*)  d_in[2];
    const float* pre_state = (const float*)d_in[3];
    const float* ppc       = (const float*)d_in[4];
    const float* table     = (const float*)d_in[5];
    const float* W_aw = (const float*)d_in[6];  const float* b_aw = (const float*)d_in[7];
    const float* W_ac = (const float*)d_in[8];  const float* b_ac = (const float*)d_in[9];
    const float* W_ih = (const float*)d_in[10]; const float* b_ih = (const float*)d_in[11];
    const float* W_hh = (const float*)d_in[12]; const float* b_hh = (const float*)d_in[13];
    const float* W_o  = (const float*)d_in[14]; const float* b_o  = (const float*)d_in[15];
    const float* W_c  = (const float*)d_in[16]; const float* b_c  = (const float*)d_in[17];
    float* out = (float*)d_out;

    float *x1, *x, *part;
    cudaGetSymbolAddress((void**)&x1,   g_x1);
    cudaGetSymbolAddress((void**)&x,    g_x);
    cudaGetSymbolAddress((void**)&part, g_part);

    // L1: aw + gh + scoreF[0..169]
    mega1<<<64 + 96 + 170, 256>>>(pre_state, W_aw, W_hh, enc, W_c, b_c);

    // L2: attention (needs aw partials) + scoreF[170..339]
    mega2<<<64 + 170, 256>>>(enc, seq, input_idx, ppc, table, b_aw, W_c, b_c);

    // L3: W_ac gemm (needs g_x1) + scoreF[340..511]
    mega3<<<32 + 172, 256>>>(x1, W_ac, enc, W_c, b_c);

    // L4: reduce W_ac partials -> g_x[:,0:512]
    splitk_reduce<<<(B_ * H_ + 255) / 256, 256>>>(b_ac, x, XW, part, H_, 8);

    // L5: gi gemm (needs g_x)
    gi_kernel<<<dim3(XW / 128, 8), 256>>>(W_ih);

    // L6: GRU (reduce gi/gh + gates) -> g_state + state output
    gru_fused<<<B_, H_>>>(pre_state, b_ih, b_hh, out + (size_t)B_ * ML_);

    // L7: score_g + scorec dot (both need g_state; F ready since L3)
    mega7<<<V_ / 128 + 64, 256>>>(W_o, b_o);

    // L8: softmax + outputs
    softmax_probc<<<B_, 1024>>>(seq, out);
}

// round 13
// speedup vs baseline: 1.2865x; 1.2865x over previous
#include <cuda_runtime.h>
#include <cuda_bf16.h>
#include <cstdint>
#include <cstddef>

#define B_   64
#define S_   256
#define H_   512
#define E_   256
#define V_   32000
#define ML_  32256
#define D2H  1024
#define XW   1536
#define X1W  1280

// warp-level bf16 HMMA, fp32 accumulate (baseline PTX feature on sm_103)
#define MMA_BF16(d, a, b) \
    asm volatile("mma.sync.aligned.m16n8k16.row.col.f32.bf16.bf16.f32 " \
        "{%0,%1,%2,%3}, {%4,%5,%6,%7}, {%8,%9}, {%0,%1,%2,%3};" \
        : "+f"((d)[0]), "+f"((d)[1]), "+f"((d)[2]), "+f"((d)[3]) \
        : "r"((a)[0]), "r"((a)[1]), "r"((a)[2]), "r"((a)[3]), "r"((b)[0]), "r"((b)[1]))

__device__ __forceinline__ void split4(float4 v, uint2& hi, uint2& lo) {
    __nv_bfloat162 h01 = make_bfloat162(__float2bfloat16(v.x), __float2bfloat16(v.y));
    __nv_bfloat162 h23 = make_bfloat162(__float2bfloat16(v.z), __float2bfloat16(v.w));
    __nv_bfloat162 l01 = make_bfloat162(
        __float2bfloat16(v.x - __bfloat162float(h01.x)),
        __float2bfloat16(v.y - __bfloat162float(h01.y)));
    __nv_bfloat162 l23 = make_bfloat162(
        __float2bfloat16(v.z - __bfloat162float(h23.x)),
        __float2bfloat16(v.w - __bfloat162float(h23.y)));
    hi = make_uint2(*(uint32_t*)&h01, *(uint32_t*)&h23);
    lo = make_uint2(*(uint32_t*)&l01, *(uint32_t*)&l23);
}

// ---- scratch ----
__device__ float g_x1[B_ * X1W];
__device__ float g_x [B_ * XW];
__device__ float g_state[B_ * H_];
__device__ float g_logits[B_ * ML_];
__device__ float g_part [8 * B_ * XW];
__device__ float g_part2[8 * B_ * XW];
__device__ float g_scpart[4 * B_ * S_];

// ---- generic HMMA GEMM body: C[64,N] = A[64,K] @ B[N,K]^T, bf16 3-split ----
#define HS 72
__device__ __forceinline__ void hmma64_body(
    const float* __restrict__ A, int lda, const float* __restrict__ Bm,
    const float* __restrict__ bias, float* __restrict__ C, int ldc,
    float* __restrict__ P, int N, int K, int kSplit,
    int bx, int by, uint8_t* __restrict__ smem)
{
    uint8_t* AhiS = smem;
    uint8_t* AloS = smem + 64 * HS;
    uint8_t* BhiS = smem + 128 * HS;
    uint8_t* BloS = smem + 256 * HS;

    const int tid = threadIdx.x, wid = tid >> 5, lane = tid & 31;
    const int g = lane >> 2, tg = lane & 3;
    const int wm = wid >> 2, wn = wid & 3;
    const int n0 = bx * 128;
    const int kLen = K / kSplit, k0 = by * kLen;
    const int nch = kLen >> 5;

    const int lrow = tid >> 1, lhalf = tid & 1;
    const float* Bsrc = Bm + (size_t)(n0 + lrow) * K + k0 + lhalf * 16;
    uint8_t* BdH = BhiS + lrow * HS + lhalf * 32;
    uint8_t* BdL = BloS + lrow * HS + lhalf * 32;
    const float* Asrc = A + (size_t)lrow * lda + k0 + lhalf * 16;
    uint8_t* AdH = AhiS + lrow * HS + lhalf * 32;
    uint8_t* AdL = AloS + lrow * HS + lhalf * 32;

    float acc[2][4][4];
    #pragma unroll
    for (int mi = 0; mi < 2; mi++)
        #pragma unroll
        for (int ni = 0; ni < 4; ni++)
            #pragma unroll
            for (int q = 0; q < 4; q++) acc[mi][ni][q] = 0.f;

    for (int kc = 0; kc < nch; kc++) {
        #pragma unroll
        for (int i = 0; i < 4; i++) {
            uint2 hi, lo;
            split4(*(const float4*)(Bsrc + kc * 32 + i * 4), hi, lo);
            *(uint2*)(BdH + i * 8) = hi;
            *(uint2*)(BdL + i * 8) = lo;
            if (tid < 128) {
                split4(*(const float4*)(Asrc + kc * 32 + i * 4), hi, lo);
                *(uint2*)(AdH + i * 8) = hi;
                *(uint2*)(AdL + i * 8) = lo;
            }
        }
        __syncthreads();
        #pragma unroll
        for (int ks = 0; ks < 2; ks++) {
            const int ko = ks * 32 + tg * 4;
            uint32_t ah[2][4], al[2][4];
            #pragma unroll
            for (int mi = 0; mi < 2; mi++) {
                const uint8_t* p = AhiS + (size_t)(wm * 32 + mi * 16 + g) * HS + ko;
                const uint8_t* q = AloS + (size_t)(wm * 32 + mi * 16 + g) * HS + ko;
                ah[mi][0] = *(const uint32_t*)(p);
                ah[mi][1] = *(const uint32_t*)(p + 8 * HS);
                ah[mi][2] = *(const uint32_t*)(p + 16);
                ah[mi][3] = *(const uint32_t*)(p + 8 * HS + 16);
                al[mi][0] = *(const uint32_t*)(q);
                al[mi][1] = *(const uint32_t*)(q + 8 * HS);
                al[mi][2] = *(const uint32_t*)(q + 16);
                al[mi][3] = *(const uint32_t*)(q + 8 * HS + 16);
            }
            #pragma unroll
            for (int ni = 0; ni < 4; ni++) {
                const uint8_t* p = BhiS + (size_t)(wn * 32 + ni * 8 + g) * HS + ko;
                const uint8_t* q = BloS + (size_t)(wn * 32 + ni * 8 + g) * HS + ko;
                uint32_t bh[2] = { *(const uint32_t*)(p), *(const uint32_t*)(p + 16) };
                uint32_t bl[2] = { *(const uint32_t*)(q), *(const uint32_t*)(q + 16) };
                #pragma unroll
                for (int mi = 0; mi < 2; mi++) {
                    MMA_BF16(acc[mi][ni], ah[mi], bh);
                    MMA_BF16(acc[mi][ni], ah[mi], bl);
                    MMA_BF16(acc[mi][ni], al[mi], bh);
                }
            }
        }
        __syncthreads();
    }

    if (kSplit == 1) {
        #pragma unroll
        for (int mi = 0; mi < 2; mi++) {
            int r = wm * 32 + mi * 16 + g;
            #pragma unroll
            for (int ni = 0; ni < 4; ni++) {
                int c = n0 + wn * 32 + ni * 8 + 2 * tg;
                float b0 = bias ? bias[c] : 0.f, b1 = bias ? bias[c+1] : 0.f;
                C[(size_t)r * ldc + c]           = acc[mi][ni][0] + b0;
                C[(size_t)r * ldc + c + 1]       = acc[mi][ni][1] + b1;
                C[(size_t)(r + 8) * ldc + c]     = acc[mi][ni][2] + b0;
                C[(size_t)(r + 8) * ldc + c + 1] = acc[mi][ni][3] + b1;
            }
        }
    } else {
        float* Pz = P + (size_t)by * 64 * N;
        #pragma unroll
        for (int mi = 0; mi < 2; mi++) {
            int r = wm * 32 + mi * 16 + g;
            #pragma unroll
            for (int ni = 0; ni < 4; ni++) {
                int c = n0 + wn * 32 + ni * 8 + 2 * tg;
                Pz[(size_t)r * N + c]           = acc[mi][ni][0];
                Pz[(size_t)r * N + c + 1]       = acc[mi][ni][1];
                Pz[(size_t)(r + 8) * N + c]     = acc[mi][ni][2];
                Pz[(size_t)(r + 8) * N + c + 1] = acc[mi][ni][3];
            }
        }
    }
}

// ---- score_c body (validated R7 math, writes g_scpart) ----
__device__ __forceinline__ void score_c_body(
    const float* __restrict__ enc, const float* __restrict__ W_c,
    const float* __restrict__ b_c, const float* __restrict__ state,
    int sx, int ny, int b, uint8_t* __restrict__ smem)
{
    uint8_t* Ahi = smem;
    uint8_t* Alo = smem + 128 * HS;
    uint8_t* Bhi = smem + 256 * HS;
    uint8_t* Blo = smem + 384 * HS;
    float (*red)[5] = (float(*)[5])(smem + 512 * HS);

    const int tid  = threadIdx.x;
    const int wid  = tid >> 5, lane = tid & 31;
    const int g    = lane >> 2, tg = lane & 3;
    const int wm   = wid >> 2,  wn = wid & 3;
    const int s0   = sx * 128, n0 = ny * 128;

    const int lrow = tid >> 1, lhalf = tid & 1;
    const float* Asrc = enc + ((size_t)(b * S_ + s0 + lrow)) * D2H + lhalf * 16;
    const float* Bsrc = W_c + ((size_t)(n0 + lrow)) * D2H + lhalf * 16;
    uint8_t* AdH = Ahi + lrow * HS + lhalf * 32;
    uint8_t* AdL = Alo + lrow * HS + lhalf * 32;
    uint8_t* BdH = Bhi + lrow * HS + lhalf * 32;
    uint8_t* BdL = Blo + lrow * HS + lhalf * 32;

    float acc[4][4][4];
    #pragma unroll
    for (int mi = 0; mi < 4; mi++)
        #pragma unroll
        for (int ni = 0; ni < 4; ni++)
            #pragma unroll
            for (int q = 0; q < 4; q++) acc[mi][ni][q] = 0.f;

    for (int kc = 0; kc < 32; kc++) {
        #pragma unroll
        for (int i = 0; i < 4; i++) {
            uint2 hi, lo;
            split4(*(const float4*)(Asrc + kc * 32 + i * 4), hi, lo);
            *(uint2*)(AdH + i * 8) = hi;
            *(uint2*)(AdL + i * 8) = lo;
            split4(*(const float4*)(Bsrc + kc * 32 + i * 4), hi, lo);
            *(uint2*)(BdH + i * 8) = hi;
            *(uint2*)(BdL + i * 8) = lo;
        }
        __syncthreads();
        #pragma unroll
        for (int ks = 0; ks < 2; ks++) {
            const int ko = ks * 32 + tg * 4;
            uint32_t ah[4][4], al[4][4];
            #pragma unroll
            for (int mi = 0; mi < 4; mi++) {
                const uint8_t* p = Ahi + (size_t)(wm * 64 + mi * 16 + g) * HS + ko;
                const uint8_t* q = Alo + (size_t)(wm * 64 + mi * 16 + g) * HS + ko;
                ah[mi][0] = *(const uint32_t*)(p);
                ah[mi][1] = *(const uint32_t*)(p + 8 * HS);
                ah[mi][2] = *(const uint32_t*)(p + 16);
                ah[mi][3] = *(const uint32_t*)(p + 8 * HS + 16);
                al[mi][0] = *(const uint32_t*)(q);
                al[mi][1] = *(const uint32_t*)(q + 8 * HS);
                al[mi][2] = *(const uint32_t*)(q + 16);
                al[mi][3] = *(const uint32_t*)(q + 8 * HS + 16);
            }
            #pragma unroll
            for (int ni = 0; ni < 4; ni++) {
                const uint8_t* p = Bhi + (size_t)(wn * 32 + ni * 8 + g) * HS + ko;
                const uint8_t* q = Blo + (size_t)(wn * 32 + ni * 8 + g) * HS + ko;
                uint32_t bh[2] = { *(const uint32_t*)(p), *(const uint32_t*)(p + 16) };
                uint32_t bl[2] = { *(const uint32_t*)(q), *(const uint32_t*)(q + 16) };
                #pragma unroll
                for (int mi = 0; mi < 4; mi++) {
                    MMA_BF16(acc[mi][ni], ah[mi], bh);
                    MMA_BF16(acc[mi][ni], ah[mi], bl);
                    MMA_BF16(acc[mi][ni], al[mi], bh);
                }
            }
        }
        __syncthreads();
    }

    float pr[4][2];
    #pragma unroll
    for (int mi = 0; mi < 4; mi++) { pr[mi][0] = 0.f; pr[mi][1] = 0.f; }
    #pragma unroll
    for (int ni = 0; ni < 4; ni++) {
        int c0 = n0 + wn * 32 + ni * 8 + 2 * tg;
        float bc0 = b_c[c0], bc1 = b_c[c0 + 1];
        float st0 = state[(size_t)b * H_ + c0], st1 = state[(size_t)b * H_ + c0 + 1];
        #pragma unroll
        for (int mi = 0; mi < 4; mi++) {
            pr[mi][0] += tanhf(acc[mi][ni][0] + bc0) * st0 + tanhf(acc[mi][ni][1] + bc1) * st1;
            pr[mi][1] += tanhf(acc[mi][ni][2] + bc0) * st0 + tanhf(acc[mi][ni][3] + bc1) * st1;
        }
    }
    #pragma unroll
    for (int mi = 0; mi < 4; mi++) {
        #pragma unroll
        for (int h = 0; h < 2; h++) {
            float v = pr[mi][h];
            v += __shfl_xor_sync(0xffffffffu, v, 1);
            v += __shfl_xor_sync(0xffffffffu, v, 2);
            if (tg == 0) red[wm * 64 + mi * 16 + h * 8 + g][wn] = v;
        }
    }
    __syncthreads();
    if (tid < 128) {
        float s = red[tid][0] + red[tid][1] + red[tid][2] + red[tid][3];
        g_scpart[(size_t)ny * (B_ * S_) + b * S_ + s0 + tid] = s;
    }
}

// ---- merged scores: score_g (blocks 0..249) + score_c (blocks 250..761) -----
#define SG_BLOCKS (V_ / 128)
__global__ void __launch_bounds__(256) scores_kernel(
    const float* __restrict__ W_o, const float* __restrict__ b_o,
    const float* __restrict__ enc, const float* __restrict__ W_c,
    const float* __restrict__ b_c)
{
    __shared__ __align__(16) uint8_t smem[512 * HS + 128 * 5 * 4];
    if (blockIdx.x < SG_BLOCKS) {
        hmma64_body(g_state, H_, W_o, b_o, g_logits, ML_, nullptr,
                    V_, H_, 1, blockIdx.x, 0, smem);
    } else {
        int idx = blockIdx.x - SG_BLOCKS;          // 0..511
        score_c_body(enc, W_c, b_c, g_state, idx & 1, (idx >> 1) & 3, idx >> 3, smem);
    }
}

// ---- fused attention: direct strength GEMV + embed + scores + softmax + ctx/sel
__global__ void __launch_bounds__(1024) attn_fused(
    const float* __restrict__ enc, const int* __restrict__ seq,
    const int* __restrict__ input_idx, const float* __restrict__ ppc,
    const float* __restrict__ table, const float* __restrict__ b_aw,
    const float* __restrict__ pre_state, const float* __restrict__ W_aw)
{
    __shared__ float ps[H_];
    __shared__ float sm[D2H];
    __shared__ float w[S_], sw[S_];
    __shared__ float red[S_];
    const int b = blockIdx.x, t = threadIdx.x;
    const int warp = t >> 5, lane = t & 31;

    if (t < E_) {
        int idx = input_idx[b];
        if (idx >= V_) idx = 2;
        g_x1[b * X1W + D2H + t] = table[(size_t)idx * E_ + t];
    }
    if (t < H_) ps[t] = pre_state[b * H_ + t];
    if (t < S_) {
        int idxb = input_idx[b];
        sw[t] = (seq[b * S_ + t] == idxb) ? ppc[b * S_ + t] : 0.f;
    }
    __syncthreads();

    // strength[d] = b_aw[d] + pre_state[b,:] . W_aw[d,:]  (warp per output)
    #pragma unroll
    for (int r = 0; r < 32; r++) {
        int d = r * 32 + warp;
        const float4* wrow = (const float4*)(W_aw + (size_t)d * H_);
        float sum = 0.f;
        #pragma unroll
        for (int qi = 0; qi < 4; qi++) {
            int q = lane + qi * 32;
            float4 v = wrow[q];
            sum += v.x*ps[q*4] + v.y*ps[q*4+1] + v.z*ps[q*4+2] + v.w*ps[q*4+3];
        }
        #pragma unroll
        for (int o = 16; o; o >>= 1) sum += __shfl_down_sync(0xffffffffu, sum, o);
        if (lane == 0) sm[d] = sum + b_aw[d];
    }
    __syncthreads();

    // attn scores: 32 warps x 8 rows
    #pragma unroll
    for (int r = 0; r < 8; r++) {
        int s = warp * 8 + r;
        const float4* row = (const float4*)(enc + ((size_t)b * S_ + s) * D2H);
        float sum = 0.f;
        #pragma unroll
        for (int qi = 0; qi < 8; qi++) {
            int q = lane + qi * 32;
            float4 v = row[q];
            sum += v.x*sm[q*4] + v.y*sm[q*4+1] + v.z*sm[q*4+2] + v.w*sm[q*4+3];
        }
        #pragma unroll
        for (int o = 16; o; o >>= 1) sum += __shfl_down_sync(0xffffffffu, sum, o);
        if (lane == 0) w[s] = sum;
    }
    __syncthreads();

    // softmax over 256
    if (t < S_) red[t] = w[t];
    __syncthreads();
    for (int o = 128; o; o >>= 1) { if (t < o) red[t] = fmaxf(red[t], red[t+o]); __syncthreads(); }
    float mx = red[0];
    __syncthreads();
    if (t < S_) { w[t] = expf(w[t] - mx); red[t] = w[t]; }
    __syncthreads();
    for (int o = 128; o; o >>= 1) { if (t < o) red[t] += red[t+o]; __syncthreads(); }
    float inv = 1.f / red[0];
    __syncthreads();
    if (t < S_) w[t] *= inv;
    __syncthreads();

    // context + select readings (d = t, unroll 8 for MLP)
    const float* e = enc + (size_t)b * S_ * D2H + t;
    float ctx = 0.f, sel = 0.f;
    #pragma unroll 8
    for (int s = 0; s < S_; s++) {
        float v = e[(size_t)s * D2H];
        ctx = fmaf(w[s], v, ctx);
        sel = fmaf(sw[s], v, sel);
    }
    g_x1[b * X1W + t]     = ctx;
    g_x [b * XW + H_ + t] = sel;
}

// ---- L2: W_ac gemm (32 blocks, needs g_x1) + gh gemm (96 blocks, independent)
__global__ void __launch_bounds__(256) wac_gh_kernel(
    const float* __restrict__ x1, const float* __restrict__ W_ac,
    const float* __restrict__ pre_state, const float* __restrict__ W_hh)
{
    __shared__ __align__(16) uint8_t smem[384 * HS];
    int i = blockIdx.x;
    if (i < 32)
        hmma64_body(x1, X1W, W_ac, nullptr, nullptr, 0, g_part, H_, X1W, 8,
                    i & 3, i >> 2, smem);
    else {
        int j = i - 32;
        hmma64_body(pre_state, H_, W_hh, nullptr, nullptr, 0, g_part2, XW, H_, 8,
                    j % 12, j / 12, smem);
    }
}

__global__ void splitk_reduce(const float* __restrict__ bias,
                              float* __restrict__ C, int ldc,
                              const float* __restrict__ P, int N, int kSplit)
{
    int idx = blockIdx.x * blockDim.x + threadIdx.x;
    int total = 64 * N;
    if (idx >= total) return;
    int m = idx / N, n = idx - m * N;
    float s = bias ? bias[n] : 0.f;
    for (int z = 0; z < kSplit; z++) s += P[(size_t)z * total + idx];
    C[(size_t)m * ldc + n] = s;
}

// ---- gi gemm ----
__global__ void __launch_bounds__(256) gi_kernel(const float* __restrict__ W_ih)
{
    __shared__ __align__(16) uint8_t smem[384 * HS];
    hmma64_body(g_x, XW, W_ih, nullptr, nullptr, 0, g_part, XW, XW, 8,
                blockIdx.x, blockIdx.y, smem);
}

// ---- fused GRU: gi/gh splitK reduce + gates ----
__global__ void __launch_bounds__(512) gru_fused(
    const float* __restrict__ pre_state,
    const float* __restrict__ b_ih, const float* __restrict__ b_hh,
    float* __restrict__ out_state)
{
    const int b = blockIdx.x, h = threadIdx.x;
    float ir = b_ih[h], iz = b_ih[H_ + h], in_ = b_ih[2*H_ + h];
    float hr = b_hh[h], hz = b_hh[H_ + h], hn  = b_hh[2*H_ + h];
    #pragma unroll
    for (int z = 0; z < 8; z++) {
        size_t base = (size_t)z * 64 * XW + (size_t)b * XW;
        ir  += g_part [base + h];
        iz  += g_part [base + H_ + h];
        in_ += g_part [base + 2*H_ + h];
        hr  += g_part2[base + h];
        hz  += g_part2[base + H_ + h];
        hn  += g_part2[base + 2*H_ + h];
    }
    float r = 1.f / (1.f + expf(-(ir + hr)));
    float z = 1.f / (1.f + expf(-(iz + hz)));
    float n = tanhf(in_ + r * hn);
    float ps = pre_state[b * H_ + h];
    float st = (1.f - z) * n + z * ps;
    g_state[b * H_ + h] = st;
    out_state[b * H_ + h] = st;
}

// ---- fused: scred + big softmax + prob_g write + prob_c scatter ----
__global__ void __launch_bounds__(1024) softmax_probc(
    const int* __restrict__ seq, float* __restrict__ out)
{
    const int b = blockIdx.x, t = threadIdx.x;
    float* row = g_logits + (size_t)b * ML_;
    float* orow = out + (size_t)b * ML_;
    __shared__ float sred[32];
    __shared__ float pc[S_];
    __shared__ int   sq[S_];

    if (t < S_) {
        int idx = b * S_ + t;
        row[V_ + t] = g_scpart[idx] + g_scpart[B_*S_ + idx]
                    + g_scpart[2*B_*S_ + idx] + g_scpart[3*B_*S_ + idx];
        sq[t] = seq[b * S_ + t];
    }
    __syncthreads();

    float m = -1e30f;
    for (int i = t; i < ML_; i += 1024) m = fmaxf(m, row[i]);
    #pragma unroll
    for (int o = 16; o; o >>= 1) m = fmaxf(m, __shfl_xor_sync(0xffffffffu, m, o));
    if ((t & 31) == 0) sred[t >> 5] = m;
    __syncthreads();
    if (t < 32) {
        float x = sred[t];
        #pragma unroll
        for (int o = 16; o; o >>= 1) x = fmaxf(x, __shfl_xor_sync(0xffffffffu, x, o));
        sred[t] = x;
    }
    __syncthreads();
    m = sred[0];
    __syncthreads();
    float sum = 0.f;
    for (int i = t; i < ML_; i += 1024) {
        float e = expf(row[i] - m);
        row[i] = e;
        sum += e;
    }
    #pragma unroll
    for (int o = 16; o; o >>= 1) sum += __shfl_xor_sync(0xffffffffu, sum, o);
    if ((t & 31) == 0) sred[t >> 5] = sum;
    __syncthreads();
    if (t < 32) {
        float x = sred[t];
        #pragma unroll
        for (int o = 16; o; o >>= 1) x += __shfl_xor_sync(0xffffffffu, x, o);
        sred[t] = x;
    }
    __syncthreads();
    float inv = 1.f / sred[0];
    for (int i = t; i < ML_; i += 1024) {
        float v = row[i] * inv;
        if (i < V_) orow[i] = v;
        else { orow[i] = 0.f; pc[i - V_] = v; }
    }
    __syncthreads();

    if (t < S_) {
        int tok = sq[t];
        float s = 0.f;
        bool first = true;
        for (int i = 0; i < S_; i++) {
            bool mq = (sq[i] == tok);
            if (mq) s += pc[i];
            if (mq && i < t) first = false;
        }
        out[(size_t)B_ * ML_ + (size_t)B_ * H_ + b * S_ + t] = s;
        if (first) orow[tok] += s;
    }
}

// ---- launch ----
extern "C" void kernel_launch(void* const* d_in, const int* in_sizes, int n_in,
                              void* d_out, int out_size)
{
    const int*   input_idx = (const int*)  d_in[0];
    const float* enc       = (const float*)d_in[1];
    const int*   seq       = (const int*)  d_in[2];
    const float* pre_state = (const float*)d_in[3];
    const float* ppc       = (const float*)d_in[4];
    const float* table     = (const float*)d_in[5];
    const float* W_aw = (const float*)d_in[6];  const float* b_aw = (const float*)d_in[7];
    const float* W_ac = (const float*)d_in[8];  const float* b_ac = (const float*)d_in[9];
    const float* W_ih = (const float*)d_in[10]; const float* b_ih = (const float*)d_in[11];
    const float* W_hh = (const float*)d_in[12]; const float* b_hh = (const float*)d_in[13];
    const float* W_o  = (const float*)d_in[14]; const float* b_o  = (const float*)d_in[15];
    const float* W_c  = (const float*)d_in[16]; const float* b_c  = (const float*)d_in[17];
    float* out = (float*)d_out;

    float *x1, *x, *part;
    cudaGetSymbolAddress((void**)&x1,   g_x1);
    cudaGetSymbolAddress((void**)&x,    g_x);
    cudaGetSymbolAddress((void**)&part, g_part);

    // L1: fused attention (direct strength GEMV, no aw pre-pass)
    attn_fused<<<B_, 1024>>>(enc, seq, input_idx, ppc, table, b_aw, pre_state, W_aw);

    // L2: W_ac gemm + gh gemm packed (homogeneous hmma64 blocks, <1 wave)
    wac_gh_kernel<<<32 + 96, 256>>>(x1, W_ac, pre_state, W_hh);

    // L3: reduce W_ac partials -> g_x[:,0:512]
    splitk_reduce<<<(B_ * H_ + 255) / 256, 256>>>(b_ac, x, XW, part, H_, 8);

    // L4: gi gemm (needs g_x)
    gi_kernel<<<dim3(XW / 128, 8), 256>>>(W_ih);

    // L5: GRU (reduce gi/gh + gates) -> g_state + state output
    gru_fused<<<B_, H_>>>(pre_state, b_ih, b_hh, out + (size_t)B_ * ML_);

    // L6: merged score_g + score_c
    scores_kernel<<<SG_BLOCKS + 512, 256>>>(W_o, b_o, enc, W_c, b_c);

    // L7: softmax + outputs
    softmax_probc<<<B_, 1024>>>(seq, out);
}

// round 14
// speedup vs baseline: 1.3338x; 1.0367x over previous
#include <cuda_runtime.h>
#include <cuda_bf16.h>
#include <cstdint>
#include <cstddef>

#define B_   64
#define S_   256
#define H_   512
#define E_   256
#define V_   32000
#define ML_  32256
#define D2H  1024
#define XW   1536
#define X1W  1280

// warp-level bf16 HMMA, fp32 accumulate (baseline PTX feature on sm_103)
#define MMA_BF16(d, a, b) \
    asm volatile("mma.sync.aligned.m16n8k16.row.col.f32.bf16.bf16.f32 " \
        "{%0,%1,%2,%3}, {%4,%5,%6,%7}, {%8,%9}, {%0,%1,%2,%3};" \
        : "+f"((d)[0]), "+f"((d)[1]), "+f"((d)[2]), "+f"((d)[3]) \
        : "r"((a)[0]), "r"((a)[1]), "r"((a)[2]), "r"((a)[3]), "r"((b)[0]), "r"((b)[1]))

__device__ __forceinline__ void split4(float4 v, uint2& hi, uint2& lo) {
    __nv_bfloat162 h01 = make_bfloat162(__float2bfloat16(v.x), __float2bfloat16(v.y));
    __nv_bfloat162 h23 = make_bfloat162(__float2bfloat16(v.z), __float2bfloat16(v.w));
    __nv_bfloat162 l01 = make_bfloat162(
        __float2bfloat16(v.x - __bfloat162float(h01.x)),
        __float2bfloat16(v.y - __bfloat162float(h01.y)));
    __nv_bfloat162 l23 = make_bfloat162(
        __float2bfloat16(v.z - __bfloat162float(h23.x)),
        __float2bfloat16(v.w - __bfloat162float(h23.y)));
    hi = make_uint2(*(uint32_t*)&h01, *(uint32_t*)&h23);
    lo = make_uint2(*(uint32_t*)&l01, *(uint32_t*)&l23);
}

// ---- scratch ----
__device__ float g_x1[B_ * X1W];
__device__ float g_x [B_ * XW];
__device__ float g_state[B_ * H_];
__device__ float g_logits[B_ * ML_];
__device__ float g_part [8 * B_ * XW];
__device__ float g_part2[8 * B_ * XW];
__device__ float g_scpart[4 * B_ * S_];

// ---- generic HMMA GEMM body with register prefetch ------------------------
#define HS 72
__device__ __forceinline__ void hmma64_body(
    const float* __restrict__ A, int lda, const float* __restrict__ Bm,
    const float* __restrict__ bias, float* __restrict__ C, int ldc,
    float* __restrict__ P, int N, int K, int kSplit,
    int bx, int by, uint8_t* __restrict__ smem)
{
    uint8_t* AhiS = smem;
    uint8_t* AloS = smem + 64 * HS;
    uint8_t* BhiS = smem + 128 * HS;
    uint8_t* BloS = smem + 256 * HS;

    const int tid = threadIdx.x, wid = tid >> 5, lane = tid & 31;
    const int g = lane >> 2, tg = lane & 3;
    const int wm = wid >> 2, wn = wid & 3;
    const int n0 = bx * 128;
    const int kLen = K / kSplit, k0 = by * kLen;
    const int nch = kLen >> 5;

    const int lrow = tid >> 1, lhalf = tid & 1;
    const float* Bsrc = Bm + (size_t)(n0 + lrow) * K + k0 + lhalf * 16;
    uint8_t* BdH = BhiS + lrow * HS + lhalf * 32;
    uint8_t* BdL = BloS + lrow * HS + lhalf * 32;
    const float* Asrc = A + (size_t)lrow * lda + k0 + lhalf * 16;
    uint8_t* AdH = AhiS + lrow * HS + lhalf * 32;
    uint8_t* AdL = AloS + lrow * HS + lhalf * 32;

    float acc[2][4][4];
    #pragma unroll
    for (int mi = 0; mi < 2; mi++)
        #pragma unroll
        for (int ni = 0; ni < 4; ni++)
            #pragma unroll
            for (int q = 0; q < 4; q++) acc[mi][ni][q] = 0.f;

    // prefetch chunk 0
    float4 rb[4], ra[4];
    #pragma unroll
    for (int i = 0; i < 4; i++) {
        rb[i] = *(const float4*)(Bsrc + i * 4);
        if (tid < 128) ra[i] = *(const float4*)(Asrc + i * 4);
    }

    for (int kc = 0; kc < nch; kc++) {
        // convert + store current regs to smem
        #pragma unroll
        for (int i = 0; i < 4; i++) {
            uint2 hi, lo;
            split4(rb[i], hi, lo);
            *(uint2*)(BdH + i * 8) = hi;
            *(uint2*)(BdL + i * 8) = lo;
            if (tid < 128) {
                split4(ra[i], hi, lo);
                *(uint2*)(AdH + i * 8) = hi;
                *(uint2*)(AdL + i * 8) = lo;
            }
        }
        __syncthreads();
        // prefetch next chunk — overlaps the MMA phase below
        if (kc + 1 < nch) {
            #pragma unroll
            for (int i = 0; i < 4; i++) {
                rb[i] = *(const float4*)(Bsrc + (kc + 1) * 32 + i * 4);
                if (tid < 128) ra[i] = *(const float4*)(Asrc + (kc + 1) * 32 + i * 4);
            }
        }
        #pragma unroll
        for (int ks = 0; ks < 2; ks++) {
            const int ko = ks * 32 + tg * 4;
            uint32_t ah[2][4], al[2][4];
            #pragma unroll
            for (int mi = 0; mi < 2; mi++) {
                const uint8_t* p = AhiS + (size_t)(wm * 32 + mi * 16 + g) * HS + ko;
                const uint8_t* q = AloS + (size_t)(wm * 32 + mi * 16 + g) * HS + ko;
                ah[mi][0] = *(const uint32_t*)(p);
                ah[mi][1] = *(const uint32_t*)(p + 8 * HS);
                ah[mi][2] = *(const uint32_t*)(p + 16);
                ah[mi][3] = *(const uint32_t*)(p + 8 * HS + 16);
                al[mi][0] = *(const uint32_t*)(q);
                al[mi][1] = *(const uint32_t*)(q + 8 * HS);
                al[mi][2] = *(const uint32_t*)(q + 16);
                al[mi][3] = *(const uint32_t*)(q + 8 * HS + 16);
            }
            #pragma unroll
            for (int ni = 0; ni < 4; ni++) {
                const uint8_t* p = BhiS + (size_t)(wn * 32 + ni * 8 + g) * HS + ko;
                const uint8_t* q = BloS + (size_t)(wn * 32 + ni * 8 + g) * HS + ko;
                uint32_t bh[2] = { *(const uint32_t*)(p), *(const uint32_t*)(p + 16) };
                uint32_t bl[2] = { *(const uint32_t*)(q), *(const uint32_t*)(q + 16) };
                #pragma unroll
                for (int mi = 0; mi < 2; mi++) {
                    MMA_BF16(acc[mi][ni], ah[mi], bh);
                    MMA_BF16(acc[mi][ni], ah[mi], bl);
                    MMA_BF16(acc[mi][ni], al[mi], bh);
                }
            }
        }
        __syncthreads();
    }

    if (kSplit == 1) {
        #pragma unroll
        for (int mi = 0; mi < 2; mi++) {
            int r = wm * 32 + mi * 16 + g;
            #pragma unroll
            for (int ni = 0; ni < 4; ni++) {
                int c = n0 + wn * 32 + ni * 8 + 2 * tg;
                float b0 = bias ? bias[c] : 0.f, b1 = bias ? bias[c+1] : 0.f;
                C[(size_t)r * ldc + c]           = acc[mi][ni][0] + b0;
                C[(size_t)r * ldc + c + 1]       = acc[mi][ni][1] + b1;
                C[(size_t)(r + 8) * ldc + c]     = acc[mi][ni][2] + b0;
                C[(size_t)(r + 8) * ldc + c + 1] = acc[mi][ni][3] + b1;
            }
        }
    } else {
        float* Pz = P + (size_t)by * 64 * N;
        #pragma unroll
        for (int mi = 0; mi < 2; mi++) {
            int r = wm * 32 + mi * 16 + g;
            #pragma unroll
            for (int ni = 0; ni < 4; ni++) {
                int c = n0 + wn * 32 + ni * 8 + 2 * tg;
                Pz[(size_t)r * N + c]           = acc[mi][ni][0];
                Pz[(size_t)r * N + c + 1]       = acc[mi][ni][1];
                Pz[(size_t)(r + 8) * N + c]     = acc[mi][ni][2];
                Pz[(size_t)(r + 8) * N + c + 1] = acc[mi][ni][3];
            }
        }
    }
}

// ---- score_c body (R7 math) with register prefetch ------------------------
__device__ __forceinline__ void score_c_body(
    const float* __restrict__ enc, const float* __restrict__ W_c,
    const float* __restrict__ b_c, const float* __restrict__ state,
    int sx, int ny, int b, uint8_t* __restrict__ smem)
{
    uint8_t* Ahi = smem;
    uint8_t* Alo = smem + 128 * HS;
    uint8_t* Bhi = smem + 256 * HS;
    uint8_t* Blo = smem + 384 * HS;
    float (*red)[5] = (float(*)[5])(smem + 512 * HS);

    const int tid  = threadIdx.x;
    const int wid  = tid >> 5, lane = tid & 31;
    const int g    = lane >> 2, tg = lane & 3;
    const int wm   = wid >> 2,  wn = wid & 3;
    const int s0   = sx * 128, n0 = ny * 128;

    const int lrow = tid >> 1, lhalf = tid & 1;
    const float* Asrc = enc + ((size_t)(b * S_ + s0 + lrow)) * D2H + lhalf * 16;
    const float* Bsrc = W_c + ((size_t)(n0 + lrow)) * D2H + lhalf * 16;
    uint8_t* AdH = Ahi + lrow * HS + lhalf * 32;
    uint8_t* AdL = Alo + lrow * HS + lhalf * 32;
    uint8_t* BdH = Bhi + lrow * HS + lhalf * 32;
    uint8_t* BdL = Blo + lrow * HS + lhalf * 32;

    float acc[4][4][4];
    #pragma unroll
    for (int mi = 0; mi < 4; mi++)
        #pragma unroll
        for (int ni = 0; ni < 4; ni++)
            #pragma unroll
            for (int q = 0; q < 4; q++) acc[mi][ni][q] = 0.f;

    float4 ra[4], rb[4];
    #pragma unroll
    for (int i = 0; i < 4; i++) {
        ra[i] = *(const float4*)(Asrc + i * 4);
        rb[i] = *(const float4*)(Bsrc + i * 4);
    }

    for (int kc = 0; kc < 32; kc++) {
        #pragma unroll
        for (int i = 0; i < 4; i++) {
            uint2 hi, lo;
            split4(ra[i], hi, lo);
            *(uint2*)(AdH + i * 8) = hi;
            *(uint2*)(AdL + i * 8) = lo;
            split4(rb[i], hi, lo);
            *(uint2*)(BdH + i * 8) = hi;
            *(uint2*)(BdL + i * 8) = lo;
        }
        __syncthreads();
        if (kc + 1 < 32) {
            #pragma unroll
            for (int i = 0; i < 4; i++) {
                ra[i] = *(const float4*)(Asrc + (kc + 1) * 32 + i * 4);
                rb[i] = *(const float4*)(Bsrc + (kc + 1) * 32 + i * 4);
            }
        }
        #pragma unroll
        for (int ks = 0; ks < 2; ks++) {
            const int ko = ks * 32 + tg * 4;
            uint32_t ah[4][4], al[4][4];
            #pragma unroll
            for (int mi = 0; mi < 4; mi++) {
                const uint8_t* p = Ahi + (size_t)(wm * 64 + mi * 16 + g) * HS + ko;
                const uint8_t* q = Alo + (size_t)(wm * 64 + mi * 16 + g) * HS + ko;
                ah[mi][0] = *(const uint32_t*)(p);
                ah[mi][1] = *(const uint32_t*)(p + 8 * HS);
                ah[mi][2] = *(const uint32_t*)(p + 16);
                ah[mi][3] = *(const uint32_t*)(p + 8 * HS + 16);
                al[mi][0] = *(const uint32_t*)(q);
                al[mi][1] = *(const uint32_t*)(q + 8 * HS);
                al[mi][2] = *(const uint32_t*)(q + 16);
                al[mi][3] = *(const uint32_t*)(q + 8 * HS + 16);
            }
            #pragma unroll
            for (int ni = 0; ni < 4; ni++) {
                const uint8_t* p = Bhi + (size_t)(wn * 32 + ni * 8 + g) * HS + ko;
                const uint8_t* q = Blo + (size_t)(wn * 32 + ni * 8 + g) * HS + ko;
                uint32_t bh[2] = { *(const uint32_t*)(p), *(const uint32_t*)(p + 16) };
                uint32_t bl[2] = { *(const uint32_t*)(q), *(const uint32_t*)(q + 16) };
                #pragma unroll
                for (int mi = 0; mi < 4; mi++) {
                    MMA_BF16(acc[mi][ni], ah[mi], bh);
                    MMA_BF16(acc[mi][ni], ah[mi], bl);
                    MMA_BF16(acc[mi][ni], al[mi], bh);
                }
            }
        }
        __syncthreads();
    }

    float pr[4][2];
    #pragma unroll
    for (int mi = 0; mi < 4; mi++) { pr[mi][0] = 0.f; pr[mi][1] = 0.f; }
    #pragma unroll
    for (int ni = 0; ni < 4; ni++) {
        int c0 = n0 + wn * 32 + ni * 8 + 2 * tg;
        float bc0 = b_c[c0], bc1 = b_c[c0 + 1];
        float st0 = state[(size_t)b * H_ + c0], st1 = state[(size_t)b * H_ + c0 + 1];
        #pragma unroll
        for (int mi = 0; mi < 4; mi++) {
            pr[mi][0] += tanhf(acc[mi][ni][0] + bc0) * st0 + tanhf(acc[mi][ni][1] + bc1) * st1;
            pr[mi][1] += tanhf(acc[mi][ni][2] + bc0) * st0 + tanhf(acc[mi][ni][3] + bc1) * st1;
        }
    }
    #pragma unroll
    for (int mi = 0; mi < 4; mi++) {
        #pragma unroll
        for (int h = 0; h < 2; h++) {
            float v = pr[mi][h];
            v += __shfl_xor_sync(0xffffffffu, v, 1);
            v += __shfl_xor_sync(0xffffffffu, v, 2);
            if (tg == 0) red[wm * 64 + mi * 16 + h * 8 + g][wn] = v;
        }
    }
    __syncthreads();
    if (tid < 128) {
        float s = red[tid][0] + red[tid][1] + red[tid][2] + red[tid][3];
        g_scpart[(size_t)ny * (B_ * S_) + b * S_ + s0 + tid] = s;
    }
}

// ---- merged scores: score_c first (long blocks), score_g last ---------------
#define SG_BLOCKS (V_ / 128)
__global__ void __launch_bounds__(256) scores_kernel(
    const float* __restrict__ W_o, const float* __restrict__ b_o,
    const float* __restrict__ enc, const float* __restrict__ W_c,
    const float* __restrict__ b_c)
{
    __shared__ __align__(16) uint8_t smem[512 * HS + 128 * 5 * 4];
    if (blockIdx.x < 512) {
        int idx = blockIdx.x;
        score_c_body(enc, W_c, b_c, g_state, idx & 1, (idx >> 1) & 3, idx >> 3, smem);
    } else {
        hmma64_body(g_state, H_, W_o, b_o, g_logits, ML_, nullptr,
                    V_, H_, 1, blockIdx.x - 512, 0, smem);
    }
}

// ---- fused attention: direct strength GEMV + embed + scores + softmax + ctx/sel
__global__ void __launch_bounds__(1024) attn_fused(
    const float* __restrict__ enc, const int* __restrict__ seq,
    const int* __restrict__ input_idx, const float* __restrict__ ppc,
    const float* __restrict__ table, const float* __restrict__ b_aw,
    const float* __restrict__ pre_state, const float* __restrict__ W_aw)
{
    __shared__ float ps[H_];
    __shared__ float sm[D2H];
    __shared__ float w[S_], sw[S_];
    __shared__ float red[S_];
    const int b = blockIdx.x, t = threadIdx.x;
    const int warp = t >> 5, lane = t & 31;

    if (t < E_) {
        int idx = input_idx[b];
        if (idx >= V_) idx = 2;
        g_x1[b * X1W + D2H + t] = table[(size_t)idx * E_ + t];
    }
    if (t < H_) ps[t] = pre_state[b * H_ + t];
    if (t < S_) {
        int idxb = input_idx[b];
        sw[t] = (seq[b * S_ + t] == idxb) ? ppc[b * S_ + t] : 0.f;
    }
    __syncthreads();

    // strength[d] = b_aw[d] + pre_state[b,:] . W_aw[d,:]  (warp per output)
    #pragma unroll
    for (int r = 0; r < 32; r++) {
        int d = r * 32 + warp;
        const float4* wrow = (const float4*)(W_aw + (size_t)d * H_);
        float sum = 0.f;
        #pragma unroll
        for (int qi = 0; qi < 4; qi++) {
            int q = lane + qi * 32;
            float4 v = wrow[q];
            sum += v.x*ps[q*4] + v.y*ps[q*4+1] + v.z*ps[q*4+2] + v.w*ps[q*4+3];
        }
        #pragma unroll
        for (int o = 16; o; o >>= 1) sum += __shfl_down_sync(0xffffffffu, sum, o);
        if (lane == 0) sm[d] = sum + b_aw[d];
    }
    __syncthreads();

    // attn scores: 32 warps x 8 rows
    #pragma unroll
    for (int r = 0; r < 8; r++) {
        int s = warp * 8 + r;
        const float4* row = (const float4*)(enc + ((size_t)b * S_ + s) * D2H);
        float sum = 0.f;
        #pragma unroll
        for (int qi = 0; qi < 8; qi++) {
            int q = lane + qi * 32;
            float4 v = row[q];
            sum += v.x*sm[q*4] + v.y*sm[q*4+1] + v.z*sm[q*4+2] + v.w*sm[q*4+3];
        }
        #pragma unroll
        for (int o = 16; o; o >>= 1) sum += __shfl_down_sync(0xffffffffu, sum, o);
        if (lane == 0) w[s] = sum;
    }
    __syncthreads();

    // softmax over 256
    if (t < S_) red[t] = w[t];
    __syncthreads();
    for (int o = 128; o; o >>= 1) { if (t < o) red[t] = fmaxf(red[t], red[t+o]); __syncthreads(); }
    float mx = red[0];
    __syncthreads();
    if (t < S_) { w[t] = expf(w[t] - mx); red[t] = w[t]; }
    __syncthreads();
    for (int o = 128; o; o >>= 1) { if (t < o) red[t] += red[t+o]; __syncthreads(); }
    float inv = 1.f / red[0];
    __syncthreads();
    if (t < S_) w[t] *= inv;
    __syncthreads();

    // context + select readings (d = t, unroll 8 for MLP)
    const float* e = enc + (size_t)b * S_ * D2H + t;
    float ctx = 0.f, sel = 0.f;
    #pragma unroll 8
    for (int s = 0; s < S_; s++) {
        float v = e[(size_t)s * D2H];
        ctx = fmaf(w[s], v, ctx);
        sel = fmaf(sw[s], v, sel);
    }
    g_x1[b * X1W + t]     = ctx;
    g_x [b * XW + H_ + t] = sel;
}

// ---- L2: W_ac gemm (32 blocks, needs g_x1) + gh gemm (96 blocks, independent)
__global__ void __launch_bounds__(256) wac_gh_kernel(
    const float* __restrict__ x1, const float* __restrict__ W_ac,
    const float* __restrict__ pre_state, const float* __restrict__ W_hh)
{
    __shared__ __align__(16) uint8_t smem[384 * HS];
    int i = blockIdx.x;
    if (i < 32)
        hmma64_body(x1, X1W, W_ac, nullptr, nullptr, 0, g_part, H_, X1W, 8,
                    i & 3, i >> 2, smem);
    else {
        int j = i - 32;
        hmma64_body(pre_state, H_, W_hh, nullptr, nullptr, 0, g_part2, XW, H_, 8,
                    j % 12, j / 12, smem);
    }
}

__global__ void splitk_reduce(const float* __restrict__ bias,
                              float* __restrict__ C, int ldc,
                              const float* __restrict__ P, int N, int kSplit)
{
    int idx = blockIdx.x * blockDim.x + threadIdx.x;
    int total = 64 * N;
    if (idx >= total) return;
    int m = idx / N, n = idx - m * N;
    float s = bias ? bias[n] : 0.f;
    for (int z = 0; z < kSplit; z++) s += P[(size_t)z * total + idx];
    C[(size_t)m * ldc + n] = s;
}

// ---- gi gemm ----
__global__ void __launch_bounds__(256) gi_kernel(const float* __restrict__ W_ih)
{
    __shared__ __align__(16) uint8_t smem[384 * HS];
    hmma64_body(g_x, XW, W_ih, nullptr, nullptr, 0, g_part, XW, XW, 8,
                blockIdx.x, blockIdx.y, smem);
}

// ---- fused GRU: gi/gh splitK reduce + gates ----
__global__ void __launch_bounds__(512) gru_fused(
    const float* __restrict__ pre_state,
    const float* __restrict__ b_ih, const float* __restrict__ b_hh,
    float* __restrict__ out_state)
{
    const int b = blockIdx.x, h = threadIdx.x;
    float ir = b_ih[h], iz = b_ih[H_ + h], in_ = b_ih[2*H_ + h];
    float hr = b_hh[h], hz = b_hh[H_ + h], hn  = b_hh[2*H_ + h];
    #pragma unroll
    for (int z = 0; z < 8; z++) {
        size_t base = (size_t)z * 64 * XW + (size_t)b * XW;
        ir  += g_part [base + h];
        iz  += g_part [base + H_ + h];
        in_ += g_part [base + 2*H_ + h];
        hr  += g_part2[base + h];
        hz  += g_part2[base + H_ + h];
        hn  += g_part2[base + 2*H_ + h];
    }
    float r = 1.f / (1.f + expf(-(ir + hr)));
    float z = 1.f / (1.f + expf(-(iz + hz)));
    float n = tanhf(in_ + r * hn);
    float ps = pre_state[b * H_ + h];
    float st = (1.f - z) * n + z * ps;
    g_state[b * H_ + h] = st;
    out_state[b * H_ + h] = st;
}

// ---- fused: scred + big softmax + prob_g write + prob_c scatter ----
__global__ void __launch_bounds__(1024) softmax_probc(
    const int* __restrict__ seq, float* __restrict__ out)
{
    const int b = blockIdx.x, t = threadIdx.x;
    float* row = g_logits + (size_t)b * ML_;
    float* orow = out + (size_t)b * ML_;
    __shared__ float sred[32];
    __shared__ float pc[S_];
    __shared__ int   sq[S_];

    if (t < S_) {
        int idx = b * S_ + t;
        row[V_ + t] = g_scpart[idx] + g_scpart[B_*S_ + idx]
                    + g_scpart[2*B_*S_ + idx] + g_scpart[3*B_*S_ + idx];
        sq[t] = seq[b * S_ + t];
    }
    __syncthreads();

    float m = -1e30f;
    for (int i = t; i < ML_; i += 1024) m = fmaxf(m, row[i]);
    #pragma unroll
    for (int o = 16; o; o >>= 1) m = fmaxf(m, __shfl_xor_sync(0xffffffffu, m, o));
    if ((t & 31) == 0) sred[t >> 5] = m;
    __syncthreads();
    if (t < 32) {
        float x = sred[t];
        #pragma unroll
        for (int o = 16; o; o >>= 1) x = fmaxf(x, __shfl_xor_sync(0xffffffffu, x, o));
        sred[t] = x;
    }
    __syncthreads();
    m = sred[0];
    __syncthreads();
    float sum = 0.f;
    for (int i = t; i < ML_; i += 1024) {
        float e = expf(row[i] - m);
        row[i] = e;
        sum += e;
    }
    #pragma unroll
    for (int o = 16; o; o >>= 1) sum += __shfl_xor_sync(0xffffffffu, sum, o);
    if ((t & 31) == 0) sred[t >> 5] = sum;
    __syncthreads();
    if (t < 32) {
        float x = sred[t];
        #pragma unroll
        for (int o = 16; o; o >>= 1) x += __shfl_xor_sync(0xffffffffu, x, o);
        sred[t] = x;
    }
    __syncthreads();
    float inv = 1.f / sred[0];
    for (int i = t; i < ML_; i += 1024) {
        float v = row[i] * inv;
        if (i < V_) orow[i] = v;
        else { orow[i] = 0.f; pc[i - V_] = v; }
    }
    __syncthreads();

    if (t < S_) {
        int tok = sq[t];
        float s = 0.f;
        bool first = true;
        for (int i = 0; i < S_; i++) {
            bool mq = (sq[i] == tok);
            if (mq) s += pc[i];
            if (mq && i < t) first = false;
        }
        out[(size_t)B_ * ML_ + (size_t)B_ * H_ + b * S_ + t] = s;
        if (first) orow[tok] += s;
    }
}

// ---- launch ----
extern "C" void kernel_launch(void* const* d_in, const int* in_sizes, int n_in,
                              void* d_out, int out_size)
{
    const int*   input_idx = (const int*)  d_in[0];
    const float* enc       = (const float*)d_in[1];
    const int*   seq       = (const int*)  d_in[2];
    const float* pre_state = (const float*)d_in[3];
    const float* ppc       = (const float*)d_in[4];
    const float* table     = (const float*)d_in[5];
    const float* W_aw = (const float*)d_in[6];  const float* b_aw = (const float*)d_in[7];
    const float* W_ac = (const float*)d_in[8];  const float* b_ac = (const float*)d_in[9];
    const float* W_ih = (const float*)d_in[10]; const float* b_ih = (const float*)d_in[11];
    const float* W_hh = (const float*)d_in[12]; const float* b_hh = (const float*)d_in[13];
    const float* W_o  = (const float*)d_in[14]; const float* b_o  = (const float*)d_in[15];
    const float* W_c  = (const float*)d_in[16]; const float* b_c  = (const float*)d_in[17];
    float* out = (float*)d_out;

    float *x1, *x, *part;
    cudaGetSymbolAddress((void**)&x1,   g_x1);
    cudaGetSymbolAddress((void**)&x,    g_x);
    cudaGetSymbolAddress((void**)&part, g_part);

    // L1: fused attention (direct strength GEMV, no aw pre-pass)
    attn_fused<<<B_, 1024>>>(enc, seq, input_idx, ppc, table, b_aw, pre_state, W_aw);

    // L2: W_ac gemm + gh gemm packed (homogeneous hmma64 blocks, <1 wave)
    wac_gh_kernel<<<32 + 96, 256>>>(x1, W_ac, pre_state, W_hh);

    // L3: reduce W_ac partials -> g_x[:,0:512]
    splitk_reduce<<<(B_ * H_ + 255) / 256, 256>>>(b_ac, x, XW, part, H_, 8);

    // L4: gi gemm (needs g_x)
    gi_kernel<<<dim3(XW / 128, 8), 256>>>(W_ih);

    // L5: GRU (reduce gi/gh + gates) -> g_state + state output
    gru_fused<<<B_, H_>>>(pre_state, b_ih, b_hh, out + (size_t)B_ * ML_);

    // L6: merged score_c (long, first) + score_g (short, last)
    scores_kernel<<<512 + SG_BLOCKS, 256>>>(W_o, b_o, enc, W_c, b_c);

    // L7: softmax + outputs
    softmax_probc<<<B_, 1024>>>(seq, out);
}

// round 15
// speedup vs baseline: 1.3569x; 1.0173x over previous
#include <cuda_runtime.h>
#include <cuda_bf16.h>
#include <cstdint>
#include <cstddef>

#define B_   64
#define S_   256
#define H_   512
#define E_   256
#define V_   32000
#define ML_  32256
#define D2H  1024
#define XW   1536
#define X1W  1280

// warp-level bf16 HMMA, fp32 accumulate (baseline PTX feature on sm_103)
#define MMA_BF16(d, a, b) \
    asm volatile("mma.sync.aligned.m16n8k16.row.col.f32.bf16.bf16.f32 " \
        "{%0,%1,%2,%3}, {%4,%5,%6,%7}, {%8,%9}, {%0,%1,%2,%3};" \
        : "+f"((d)[0]), "+f"((d)[1]), "+f"((d)[2]), "+f"((d)[3]) \
        : "r"((a)[0]), "r"((a)[1]), "r"((a)[2]), "r"((a)[3]), "r"((b)[0]), "r"((b)[1]))

__device__ __forceinline__ void split4(float4 v, uint2& hi, uint2& lo) {
    __nv_bfloat162 h01 = make_bfloat162(__float2bfloat16(v.x), __float2bfloat16(v.y));
    __nv_bfloat162 h23 = make_bfloat162(__float2bfloat16(v.z), __float2bfloat16(v.w));
    __nv_bfloat162 l01 = make_bfloat162(
        __float2bfloat16(v.x - __bfloat162float(h01.x)),
        __float2bfloat16(v.y - __bfloat162float(h01.y)));
    __nv_bfloat162 l23 = make_bfloat162(
        __float2bfloat16(v.z - __bfloat162float(h23.x)),
        __float2bfloat16(v.w - __bfloat162float(h23.y)));
    hi = make_uint2(*(uint32_t*)&h01, *(uint32_t*)&h23);
    lo = make_uint2(*(uint32_t*)&l01, *(uint32_t*)&l23);
}

// ---- scratch ----
__device__ float g_x1[B_ * X1W];
__device__ float g_x [B_ * XW];
__device__ float g_state[B_ * H_];
__device__ float g_logits[B_ * ML_];
__device__ float g_part [8 * B_ * XW];
__device__ float g_part2[8 * B_ * XW];
__device__ float g_scpart[4 * B_ * S_];

#define HS 72
#define HM_BUF  (384 * HS)             // one hmma64 buffer (A 64 rows + B 128 rows, hi/lo)
#define HM_SMEM (2 * HM_BUF)           // 55296
#define SC_BUF  (512 * HS)             // one score_c buffer (A 128 + B 128, hi/lo)
#define SC_SMEM (2 * SC_BUF + 128 * 5 * 4)   // 76288

// ---- generic HMMA GEMM body: double-buffered smem + register prefetch -------
__device__ __forceinline__ void hmma64_body(
    const float* __restrict__ A, int lda, const float* __restrict__ Bm,
    const float* __restrict__ bias, float* __restrict__ C, int ldc,
    float* __restrict__ P, int N, int K, int kSplit,
    int bx, int by, uint8_t* __restrict__ smem)
{
    const int tid = threadIdx.x, wid = tid >> 5, lane = tid & 31;
    const int g = lane >> 2, tg = lane & 3;
    const int wm = wid >> 2, wn = wid & 3;
    const int n0 = bx * 128;
    const int kLen = K / kSplit, k0 = by * kLen;
    const int nch = kLen >> 5;

    const int lrow = tid >> 1, lhalf = tid & 1;
    const float* Bsrc = Bm + (size_t)(n0 + lrow) * K + k0 + lhalf * 16;
    const float* Asrc = A + (size_t)lrow * lda + k0 + lhalf * 16;
    // region offsets within one buffer: Ahi 0 | Alo 64*HS | Bhi 128*HS | Blo 256*HS
    const int offA = lrow * HS + lhalf * 32;
    const int offB = lrow * HS + lhalf * 32;

    float acc[2][4][4];
    #pragma unroll
    for (int mi = 0; mi < 2; mi++)
        #pragma unroll
        for (int ni = 0; ni < 4; ni++)
            #pragma unroll
            for (int q = 0; q < 4; q++) acc[mi][ni][q] = 0.f;

    float4 rb[4], ra[4];
    #pragma unroll
    for (int i = 0; i < 4; i++) {
        rb[i] = *(const float4*)(Bsrc + i * 4);
        if (tid < 128) ra[i] = *(const float4*)(Asrc + i * 4);
    }
    // store chunk 0 -> buf 0
    {
        uint8_t* buf = smem;
        #pragma unroll
        for (int i = 0; i < 4; i++) {
            uint2 hi, lo;
            split4(rb[i], hi, lo);
            *(uint2*)(buf + 128 * HS + offB + i * 8) = hi;
            *(uint2*)(buf + 256 * HS + offB + i * 8) = lo;
            if (tid < 128) {
                split4(ra[i], hi, lo);
                *(uint2*)(buf + offA + i * 8) = hi;
                *(uint2*)(buf + 64 * HS + offA + i * 8) = lo;
            }
        }
    }
    __syncthreads();

    for (int kc = 0; kc < nch; kc++) {
        const int cur = kc & 1;
        uint8_t* bufc = smem + cur * HM_BUF;
        const bool more = (kc + 1 < nch);
        if (more) {
            #pragma unroll
            for (int i = 0; i < 4; i++) {
                rb[i] = *(const float4*)(Bsrc + (kc + 1) * 32 + i * 4);
                if (tid < 128) ra[i] = *(const float4*)(Asrc + (kc + 1) * 32 + i * 4);
            }
        }
        #pragma unroll
        for (int ks = 0; ks < 2; ks++) {
            const int ko = ks * 32 + tg * 4;
            uint32_t ah[2][4], al[2][4];
            #pragma unroll
            for (int mi = 0; mi < 2; mi++) {
                const uint8_t* p = bufc + (size_t)(wm * 32 + mi * 16 + g) * HS + ko;
                const uint8_t* q = p + 64 * HS;
                ah[mi][0] = *(const uint32_t*)(p);
                ah[mi][1] = *(const uint32_t*)(p + 8 * HS);
                ah[mi][2] = *(const uint32_t*)(p + 16);
                ah[mi][3] = *(const uint32_t*)(p + 8 * HS + 16);
                al[mi][0] = *(const uint32_t*)(q);
                al[mi][1] = *(const uint32_t*)(q + 8 * HS);
                al[mi][2] = *(const uint32_t*)(q + 16);
                al[mi][3] = *(const uint32_t*)(q + 8 * HS + 16);
            }
            #pragma unroll
            for (int ni = 0; ni < 4; ni++) {
                const uint8_t* p = bufc + 128 * HS + (size_t)(wn * 32 + ni * 8 + g) * HS + ko;
                const uint8_t* q = p + 128 * HS;
                uint32_t bh[2] = { *(const uint32_t*)(p), *(const uint32_t*)(p + 16) };
                uint32_t bl[2] = { *(const uint32_t*)(q), *(const uint32_t*)(q + 16) };
                #pragma unroll
                for (int mi = 0; mi < 2; mi++) {
                    MMA_BF16(acc[mi][ni], ah[mi], bh);
                    MMA_BF16(acc[mi][ni], ah[mi], bl);
                    MMA_BF16(acc[mi][ni], al[mi], bh);
                }
            }
        }
        if (more) {
            uint8_t* bufn = smem + (cur ^ 1) * HM_BUF;
            #pragma unroll
            for (int i = 0; i < 4; i++) {
                uint2 hi, lo;
                split4(rb[i], hi, lo);
                *(uint2*)(bufn + 128 * HS + offB + i * 8) = hi;
                *(uint2*)(bufn + 256 * HS + offB + i * 8) = lo;
                if (tid < 128) {
                    split4(ra[i], hi, lo);
                    *(uint2*)(bufn + offA + i * 8) = hi;
                    *(uint2*)(bufn + 64 * HS + offA + i * 8) = lo;
                }
            }
        }
        __syncthreads();
    }

    if (kSplit == 1) {
        #pragma unroll
        for (int mi = 0; mi < 2; mi++) {
            int r = wm * 32 + mi * 16 + g;
            #pragma unroll
            for (int ni = 0; ni < 4; ni++) {
                int c = n0 + wn * 32 + ni * 8 + 2 * tg;
                float b0 = bias ? bias[c] : 0.f, b1 = bias ? bias[c+1] : 0.f;
                C[(size_t)r * ldc + c]           = acc[mi][ni][0] + b0;
                C[(size_t)r * ldc + c + 1]       = acc[mi][ni][1] + b1;
                C[(size_t)(r + 8) * ldc + c]     = acc[mi][ni][2] + b0;
                C[(size_t)(r + 8) * ldc + c + 1] = acc[mi][ni][3] + b1;
            }
        }
    } else {
        float* Pz = P + (size_t)by * 64 * N;
        #pragma unroll
        for (int mi = 0; mi < 2; mi++) {
            int r = wm * 32 + mi * 16 + g;
            #pragma unroll
            for (int ni = 0; ni < 4; ni++) {
                int c = n0 + wn * 32 + ni * 8 + 2 * tg;
                Pz[(size_t)r * N + c]           = acc[mi][ni][0];
                Pz[(size_t)r * N + c + 1]       = acc[mi][ni][1];
                Pz[(size_t)(r + 8) * N + c]     = acc[mi][ni][2];
                Pz[(size_t)(r + 8) * N + c + 1] = acc[mi][ni][3];
            }
        }
    }
}

// ---- score_c body (R7 math): double-buffered smem + register prefetch -------
__device__ __forceinline__ void score_c_body(
    const float* __restrict__ enc, const float* __restrict__ W_c,
    const float* __restrict__ b_c, const float* __restrict__ state,
    int sx, int ny, int b, uint8_t* __restrict__ smem)
{
    float (*red)[5] = (float(*)[5])(smem + 2 * SC_BUF);

    const int tid  = threadIdx.x;
    const int wid  = tid >> 5, lane = tid & 31;
    const int g    = lane >> 2, tg = lane & 3;
    const int wm   = wid >> 2,  wn = wid & 3;
    const int s0   = sx * 128, n0 = ny * 128;

    const int lrow = tid >> 1, lhalf = tid & 1;
    const float* Asrc = enc + ((size_t)(b * S_ + s0 + lrow)) * D2H + lhalf * 16;
    const float* Bsrc = W_c + ((size_t)(n0 + lrow)) * D2H + lhalf * 16;
    // regions within one buffer: Ahi 0 | Alo 128*HS | Bhi 256*HS | Blo 384*HS
    const int off = lrow * HS + lhalf * 32;

    float acc[4][4][4];
    #pragma unroll
    for (int mi = 0; mi < 4; mi++)
        #pragma unroll
        for (int ni = 0; ni < 4; ni++)
            #pragma unroll
            for (int q = 0; q < 4; q++) acc[mi][ni][q] = 0.f;

    float4 ra[4], rb[4];
    #pragma unroll
    for (int i = 0; i < 4; i++) {
        ra[i] = *(const float4*)(Asrc + i * 4);
        rb[i] = *(const float4*)(Bsrc + i * 4);
    }
    {
        uint8_t* buf = smem;
        #pragma unroll
        for (int i = 0; i < 4; i++) {
            uint2 hi, lo;
            split4(ra[i], hi, lo);
            *(uint2*)(buf + off + i * 8) = hi;
            *(uint2*)(buf + 128 * HS + off + i * 8) = lo;
            split4(rb[i], hi, lo);
            *(uint2*)(buf + 256 * HS + off + i * 8) = hi;
            *(uint2*)(buf + 384 * HS + off + i * 8) = lo;
        }
    }
    __syncthreads();

    for (int kc = 0; kc < 32; kc++) {
        const int cur = kc & 1;
        uint8_t* bufc = smem + cur * SC_BUF;
        const bool more = (kc + 1 < 32);
        if (more) {
            #pragma unroll
            for (int i = 0; i < 4; i++) {
                ra[i] = *(const float4*)(Asrc + (kc + 1) * 32 + i * 4);
                rb[i] = *(const float4*)(Bsrc + (kc + 1) * 32 + i * 4);
            }
        }
        #pragma unroll
        for (int ks = 0; ks < 2; ks++) {
            const int ko = ks * 32 + tg * 4;
            uint32_t ah[4][4], al[4][4];
            #pragma unroll
            for (int mi = 0; mi < 4; mi++) {
                const uint8_t* p = bufc + (size_t)(wm * 64 + mi * 16 + g) * HS + ko;
                const uint8_t* q = p + 128 * HS;
                ah[mi][0] = *(const uint32_t*)(p);
                ah[mi][1] = *(const uint32_t*)(p + 8 * HS);
                ah[mi][2] = *(const uint32_t*)(p + 16);
                ah[mi][3] = *(const uint32_t*)(p + 8 * HS + 16);
                al[mi][0] = *(const uint32_t*)(q);
                al[mi][1] = *(const uint32_t*)(q + 8 * HS);
                al[mi][2] = *(const uint32_t*)(q + 16);
                al[mi][3] = *(const uint32_t*)(q + 8 * HS + 16);
            }
            #pragma unroll
            for (int ni = 0; ni < 4; ni++) {
                const uint8_t* p = bufc + 256 * HS + (size_t)(wn * 32 + ni * 8 + g) * HS + ko;
                const uint8_t* q = p + 128 * HS;
                uint32_t bh[2] = { *(const uint32_t*)(p), *(const uint32_t*)(p + 16) };
                uint32_t bl[2] = { *(const uint32_t*)(q), *(const uint32_t*)(q + 16) };
                #pragma unroll
                for (int mi = 0; mi < 4; mi++) {
                    MMA_BF16(acc[mi][ni], ah[mi], bh);
                    MMA_BF16(acc[mi][ni], ah[mi], bl);
                    MMA_BF16(acc[mi][ni], al[mi], bh);
                }
            }
        }
        if (more) {
            uint8_t* bufn = smem + (cur ^ 1) * SC_BUF;
            #pragma unroll
            for (int i = 0; i < 4; i++) {
                uint2 hi, lo;
                split4(ra[i], hi, lo);
                *(uint2*)(bufn + off + i * 8) = hi;
                *(uint2*)(bufn + 128 * HS + off + i * 8) = lo;
                split4(rb[i], hi, lo);
                *(uint2*)(bufn + 256 * HS + off + i * 8) = hi;
                *(uint2*)(bufn + 384 * HS + off + i * 8) = lo;
            }
        }
        __syncthreads();
    }

    float pr[4][2];
    #pragma unroll
    for (int mi = 0; mi < 4; mi++) { pr[mi][0] = 0.f; pr[mi][1] = 0.f; }
    #pragma unroll
    for (int ni = 0; ni < 4; ni++) {
        int c0 = n0 + wn * 32 + ni * 8 + 2 * tg;
        float bc0 = b_c[c0], bc1 = b_c[c0 + 1];
        float st0 = state[(size_t)b * H_ + c0], st1 = state[(size_t)b * H_ + c0 + 1];
        #pragma unroll
        for (int mi = 0; mi < 4; mi++) {
            pr[mi][0] += tanhf(acc[mi][ni][0] + bc0) * st0 + tanhf(acc[mi][ni][1] + bc1) * st1;
            pr[mi][1] += tanhf(acc[mi][ni][2] + bc0) * st0 + tanhf(acc[mi][ni][3] + bc1) * st1;
        }
    }
    #pragma unroll
    for (int mi = 0; mi < 4; mi++) {
        #pragma unroll
        for (int h = 0; h < 2; h++) {
            float v = pr[mi][h];
            v += __shfl_xor_sync(0xffffffffu, v, 1);
            v += __shfl_xor_sync(0xffffffffu, v, 2);
            if (tg == 0) red[wm * 64 + mi * 16 + h * 8 + g][wn] = v;
        }
    }
    __syncthreads();
    if (tid < 128) {
        float s = red[tid][0] + red[tid][1] + red[tid][2] + red[tid][3];
        g_scpart[(size_t)ny * (B_ * S_) + b * S_ + s0 + tid] = s;
    }
}

// ---- merged scores: score_c first (long blocks), score_g last ---------------
#define SG_BLOCKS (V_ / 128)
__global__ void __launch_bounds__(256) scores_kernel(
    const float* __restrict__ W_o, const float* __restrict__ b_o,
    const float* __restrict__ enc, const float* __restrict__ W_c,
    const float* __restrict__ b_c)
{
    extern __shared__ __align__(16) uint8_t smem[];
    if (blockIdx.x < 512) {
        int idx = blockIdx.x;
        score_c_body(enc, W_c, b_c, g_state, idx & 1, (idx >> 1) & 3, idx >> 3, smem);
    } else {
        hmma64_body(g_state, H_, W_o, b_o, g_logits, ML_, nullptr,
                    V_, H_, 1, blockIdx.x - 512, 0, smem);
    }
}

// ---- fused attention: direct strength GEMV + embed + scores + softmax + ctx/sel
__global__ void __launch_bounds__(1024) attn_fused(
    const float* __restrict__ enc, const int* __restrict__ seq,
    const int* __restrict__ input_idx, const float* __restrict__ ppc,
    const float* __restrict__ table, const float* __restrict__ b_aw,
    const float* __restrict__ pre_state, const float* __restrict__ W_aw)
{
    __shared__ float ps[H_];
    __shared__ float sm[D2H];
    __shared__ float w[S_], sw[S_];
    __shared__ float red[S_];
    const int b = blockIdx.x, t = threadIdx.x;
    const int warp = t >> 5, lane = t & 31;

    if (t < E_) {
        int idx = input_idx[b];
        if (idx >= V_) idx = 2;
        g_x1[b * X1W + D2H + t] = table[(size_t)idx * E_ + t];
    }
    if (t < H_) ps[t] = pre_state[b * H_ + t];
    if (t < S_) {
        int idxb = input_idx[b];
        sw[t] = (seq[b * S_ + t] == idxb) ? ppc[b * S_ + t] : 0.f;
    }
    __syncthreads();

    #pragma unroll
    for (int r = 0; r < 32; r++) {
        int d = r * 32 + warp;
        const float4* wrow = (const float4*)(W_aw + (size_t)d * H_);
        float sum = 0.f;
        #pragma unroll
        for (int qi = 0; qi < 4; qi++) {
            int q = lane + qi * 32;
            float4 v = wrow[q];
            sum += v.x*ps[q*4] + v.y*ps[q*4+1] + v.z*ps[q*4+2] + v.w*ps[q*4+3];
        }
        #pragma unroll
        for (int o = 16; o; o >>= 1) sum += __shfl_down_sync(0xffffffffu, sum, o);
        if (lane == 0) sm[d] = sum + b_aw[d];
    }
    __syncthreads();

    #pragma unroll
    for (int r = 0; r < 8; r++) {
        int s = warp * 8 + r;
        const float4* row = (const float4*)(enc + ((size_t)b * S_ + s) * D2H);
        float sum = 0.f;
        #pragma unroll
        for (int qi = 0; qi < 8; qi++) {
            int q = lane + qi * 32;
            float4 v = row[q];
            sum += v.x*sm[q*4] + v.y*sm[q*4+1] + v.z*sm[q*4+2] + v.w*sm[q*4+3];
        }
        #pragma unroll
        for (int o = 16; o; o >>= 1) sum += __shfl_down_sync(0xffffffffu, sum, o);
        if (lane == 0) w[s] = sum;
    }
    __syncthreads();

    if (t < S_) red[t] = w[t];
    __syncthreads();
    for (int o = 128; o; o >>= 1) { if (t < o) red[t] = fmaxf(red[t], red[t+o]); __syncthreads(); }
    float mx = red[0];
    __syncthreads();
    if (t < S_) { w[t] = expf(w[t] - mx); red[t] = w[t]; }
    __syncthreads();
    for (int o = 128; o; o >>= 1) { if (t < o) red[t] += red[t+o]; __syncthreads(); }
    float inv = 1.f / red[0];
    __syncthreads();
    if (t < S_) w[t] *= inv;
    __syncthreads();

    const float* e = enc + (size_t)b * S_ * D2H + t;
    float ctx = 0.f, sel = 0.f;
    #pragma unroll 8
    for (int s = 0; s < S_; s++) {
        float v = e[(size_t)s * D2H];
        ctx = fmaf(w[s], v, ctx);
        sel = fmaf(sw[s], v, sel);
    }
    g_x1[b * X1W + t]     = ctx;
    g_x [b * XW + H_ + t] = sel;
}

// ---- L2: W_ac gemm (32 blocks) + gh gemm (96 blocks) ----
__global__ void __launch_bounds__(256) wac_gh_kernel(
    const float* __restrict__ x1, const float* __restrict__ W_ac,
    const float* __restrict__ pre_state, const float* __restrict__ W_hh)
{
    extern __shared__ __align__(16) uint8_t smem[];
    int i = blockIdx.x;
    if (i < 32)
        hmma64_body(x1, X1W, W_ac, nullptr, nullptr, 0, g_part, H_, X1W, 8,
                    i & 3, i >> 2, smem);
    else {
        int j = i - 32;
        hmma64_body(pre_state, H_, W_hh, nullptr, nullptr, 0, g_part2, XW, H_, 8,
                    j % 12, j / 12, smem);
    }
}

__global__ void splitk_reduce(const float* __restrict__ bias,
                              float* __restrict__ C, int ldc,
                              const float* __restrict__ P, int N, int kSplit)
{
    int idx = blockIdx.x * blockDim.x + threadIdx.x;
    int total = 64 * N;
    if (idx >= total) return;
    int m = idx / N, n = idx - m * N;
    float s = bias ? bias[n] : 0.f;
    for (int z = 0; z < kSplit; z++) s += P[(size_t)z * total + idx];
    C[(size_t)m * ldc + n] = s;
}

// ---- gi gemm ----
__global__ void __launch_bounds__(256) gi_kernel(const float* __restrict__ W_ih)
{
    extern __shared__ __align__(16) uint8_t smem[];
    hmma64_body(g_x, XW, W_ih, nullptr, nullptr, 0, g_part, XW, XW, 8,
                blockIdx.x, blockIdx.y, smem);
}

// ---- fused GRU: gi/gh splitK reduce + gates ----
__global__ void __launch_bounds__(512) gru_fused(
    const float* __restrict__ pre_state,
    const float* __restrict__ b_ih, const float* __restrict__ b_hh,
    float* __restrict__ out_state)
{
    const int b = blockIdx.x, h = threadIdx.x;
    float ir = b_ih[h], iz = b_ih[H_ + h], in_ = b_ih[2*H_ + h];
    float hr = b_hh[h], hz = b_hh[H_ + h], hn  = b_hh[2*H_ + h];
    #pragma unroll
    for (int z = 0; z < 8; z++) {
        size_t base = (size_t)z * 64 * XW + (size_t)b * XW;
        ir  += g_part [base + h];
        iz  += g_part [base + H_ + h];
        in_ += g_part [base + 2*H_ + h];
        hr  += g_part2[base + h];
        hz  += g_part2[base + H_ + h];
        hn  += g_part2[base + 2*H_ + h];
    }
    float r = 1.f / (1.f + expf(-(ir + hr)));
    float z = 1.f / (1.f + expf(-(iz + hz)));
    float n = tanhf(in_ + r * hn);
    float ps = pre_state[b * H_ + h];
    float st = (1.f - z) * n + z * ps;
    g_state[b * H_ + h] = st;
    out_state[b * H_ + h] = st;
}

// ---- fused: scred + big softmax + prob_g write + prob_c scatter ----
__global__ void __launch_bounds__(1024) softmax_probc(
    const int* __restrict__ seq, float* __restrict__ out)
{
    const int b = blockIdx.x, t = threadIdx.x;
    float* row = g_logits + (size_t)b * ML_;
    float* orow = out + (size_t)b * ML_;
    __shared__ float sred[32];
    __shared__ float pc[S_];
    __shared__ int   sq[S_];

    if (t < S_) {
        int idx = b * S_ + t;
        row[V_ + t] = g_scpart[idx] + g_scpart[B_*S_ + idx]
                    + g_scpart[2*B_*S_ + idx] + g_scpart[3*B_*S_ + idx];
        sq[t] = seq[b * S_ + t];
    }
    __syncthreads();

    float m = -1e30f;
    for (int i = t; i < ML_; i += 1024) m = fmaxf(m, row[i]);
    #pragma unroll
    for (int o = 16; o; o >>= 1) m = fmaxf(m, __shfl_xor_sync(0xffffffffu, m, o));
    if ((t & 31) == 0) sred[t >> 5] = m;
    __syncthreads();
    if (t < 32) {
        float x = sred[t];
        #pragma unroll
        for (int o = 16; o; o >>= 1) x = fmaxf(x, __shfl_xor_sync(0xffffffffu, x, o));
        sred[t] = x;
    }
    __syncthreads();
    m = sred[0];
    __syncthreads();
    float sum = 0.f;
    for (int i = t; i < ML_; i += 1024) {
        float e = expf(row[i] - m);
        row[i] = e;
        sum += e;
    }
    #pragma unroll
    for (int o = 16; o; o >>= 1) sum += __shfl_xor_sync(0xffffffffu, sum, o);
    if ((t & 31) == 0) sred[t >> 5] = sum;
    __syncthreads();
    if (t < 32) {
        float x = sred[t];
        #pragma unroll
        for (int o = 16; o; o >>= 1) x += __shfl_xor_sync(0xffffffffu, x, o);
        sred[t] = x;
    }
    __syncthreads();
    float inv = 1.f / sred[0];
    for (int i = t; i < ML_; i += 1024) {
        float v = row[i] * inv;
        if (i < V_) orow[i] = v;
        else { orow[i] = 0.f; pc[i - V_] = v; }
    }
    __syncthreads();

    if (t < S_) {
        int tok = sq[t];
        float s = 0.f;
        bool first = true;
        for (int i = 0; i < S_; i++) {
            bool mq = (sq[i] == tok);
            if (mq) s += pc[i];
            if (mq && i < t) first = false;
        }
        out[(size_t)B_ * ML_ + (size_t)B_ * H_ + b * S_ + t] = s;
        if (first) orow[tok] += s;
    }
}

// ---- launch ----
extern "C" void kernel_launch(void* const* d_in, const int* in_sizes, int n_in,
                              void* d_out, int out_size)
{
    const int*   input_idx = (const int*)  d_in[0];
    const float* enc       = (const float*)d_in[1];
    const int*   seq       = (const int*)  d_in[2];
    const float* pre_state = (const float*)d_in[3];
    const float* ppc       = (const float*)d_in[4];
    const float* table     = (const float*)d_in[5];
    const float* W_aw = (const float*)d_in[6];  const float* b_aw = (const float*)d_in[7];
    const float* W_ac = (const float*)d_in[8];  const float* b_ac = (const float*)d_in[9];
    const float* W_ih = (const float*)d_in[10]; const float* b_ih = (const float*)d_in[11];
    const float* W_hh = (const float*)d_in[12]; const float* b_hh = (const float*)d_in[13];
    const float* W_o  = (const float*)d_in[14]; const float* b_o  = (const float*)d_in[15];
    const float* W_c  = (const float*)d_in[16]; const float* b_c  = (const float*)d_in[17];
    float* out = (float*)d_out;

    float *x1, *x, *part;
    cudaGetSymbolAddress((void**)&x1,   g_x1);
    cudaGetSymbolAddress((void**)&x,    g_x);
    cudaGetSymbolAddress((void**)&part, g_part);

    // opt-in to >48KB dynamic smem (idempotent host-side attribute set)
    cudaFuncSetAttribute(scores_kernel, cudaFuncAttributeMaxDynamicSharedMemorySize, SC_SMEM);
    cudaFuncSetAttribute(wac_gh_kernel, cudaFuncAttributeMaxDynamicSharedMemorySize, HM_SMEM);
    cudaFuncSetAttribute(gi_kernel,     cudaFuncAttributeMaxDynamicSharedMemorySize, HM_SMEM);

    // L1: fused attention
    attn_fused<<<B_, 1024>>>(enc, seq, input_idx, ppc, table, b_aw, pre_state, W_aw);

    // L2: W_ac gemm + gh gemm packed
    wac_gh_kernel<<<32 + 96, 256, HM_SMEM>>>(x1, W_ac, pre_state, W_hh);

    // L3: reduce W_ac partials -> g_x[:,0:512]
    splitk_reduce<<<(B_ * H_ + 255) / 256, 256>>>(b_ac, x, XW, part, H_, 8);

    // L4: gi gemm
    gi_kernel<<<dim3(XW / 128, 8), 256, HM_SMEM>>>(W_ih);

    // L5: GRU -> g_state + state output
    gru_fused<<<B_, H_>>>(pre_state, b_ih, b_hh, out + (size_t)B_ * ML_);

    // L6: merged score_c (long, first) + score_g (short, last)
    scores_kernel<<<512 + SG_BLOCKS, 256, SC_SMEM>>>(W_o, b_o, enc, W_c, b_c);

    // L7: softmax + outputs
    softmax_probc<<<B_, 1024>>>(seq, out);
}